// round 1
// baseline (speedup 1.0000x reference)
#include <cuda_runtime.h>
#include <cuda_bf16.h>
#include <math.h>

// ---------------- problem constants ----------------
#define BB   2
#define LSEQ 2048
#define DM   768
#define NH   12
#define HD   64
#define DFF  3072
#define MROWS (BB*LSEQ)      // 4096
#define NQKV  (3*DM)         // 2304

// ---------------- scratch (static device memory, alloc-free) ----------------
__device__ float g_h   [MROWS*DM];    // LN output (reused for LN1 and LN2)
__device__ float g_qkv [MROWS*NQKV];  // qkv projection
__device__ float g_attn[MROWS*DM];    // attention output (b,l,h,d)
__device__ float g_x1  [MROWS*DM];    // x + attn proj (residual 1)
__device__ float g_ffh [MROWS*DFF];   // gelu(fc1)

// ---------------- LayerNorm: one block per row, 256 threads ----------------
__global__ void ln_kernel(const float* __restrict__ X, const float* __restrict__ g,
                          const float* __restrict__ b, float* __restrict__ Y) {
    int row = blockIdx.x;
    const float* xr = X + (size_t)row * DM;
    float v[3];
    float s = 0.f, sq = 0.f;
#pragma unroll
    for (int i = 0; i < 3; i++) {
        v[i] = xr[threadIdx.x + i * 256];
        s += v[i];
        sq += v[i] * v[i];
    }
#pragma unroll
    for (int o = 16; o > 0; o >>= 1) {
        s  += __shfl_xor_sync(0xffffffffu, s, o);
        sq += __shfl_xor_sync(0xffffffffu, sq, o);
    }
    __shared__ float red0[8], red1[8];
    int w = threadIdx.x >> 5, lane = threadIdx.x & 31;
    if (lane == 0) { red0[w] = s; red1[w] = sq; }
    __syncthreads();
    s = 0.f; sq = 0.f;
#pragma unroll
    for (int i = 0; i < 8; i++) { s += red0[i]; sq += red1[i]; }
    float mu  = s * (1.f / DM);
    float var = sq * (1.f / DM) - mu * mu;
    float inv = rsqrtf(var + 1e-5f);
    float* yr = Y + (size_t)row * DM;
#pragma unroll
    for (int i = 0; i < 3; i++) {
        int idx = threadIdx.x + i * 256;
        yr[idx] = (v[i] - mu) * inv * g[idx] + b[idx];
    }
}

// ---------------- SGEMM 128x128x8, 256 threads, 8x8 per thread ----------------
// C[M,N] = A[M,K] @ B[K,N] + bias[N]   (+ epilogue)
// EPI: 0 = bias only, 1 = bias + exact GELU, 2 = bias + residual add
template <int EPI>
__global__ void __launch_bounds__(256, 2)
sgemm_kernel(const float* __restrict__ A, const float* __restrict__ Bm,
             const float* __restrict__ bias, const float* __restrict__ res,
             float* __restrict__ C, int M, int N, int K) {
    const int BM = 128, BN = 128, BK = 8, TM = 8, TN = 8;
    __shared__ float As[BK][BM];
    __shared__ float Bs[BK][BN];

    int tid = threadIdx.x;
    int brow = blockIdx.y, bcol = blockIdx.x;
    int tx = tid & 15, ty = tid >> 4;          // 16x16 thread grid

    int aRow = tid >> 1, aCol = (tid & 1) * 4; // A tile 128x8 via float4
    int bRow = tid >> 5, bCol = (tid & 31) * 4; // B tile 8x128 via float4

    const float* Ab = A + (size_t)(brow * BM) * K;
    const float* Bb = Bm + bcol * BN;

    float acc[TM][TN];
#pragma unroll
    for (int i = 0; i < TM; i++)
#pragma unroll
        for (int j = 0; j < TN; j++) acc[i][j] = 0.f;

    for (int k0 = 0; k0 < K; k0 += BK) {
        float4 av = *(const float4*)(Ab + (size_t)aRow * K + k0 + aCol);
        As[aCol + 0][aRow] = av.x;
        As[aCol + 1][aRow] = av.y;
        As[aCol + 2][aRow] = av.z;
        As[aCol + 3][aRow] = av.w;
        float4 bv = *(const float4*)(Bb + (size_t)(k0 + bRow) * N + bCol);
        *(float4*)&Bs[bRow][bCol] = bv;
        __syncthreads();
#pragma unroll
        for (int k = 0; k < BK; k++) {
            float ar[TM], br[TN];
            *(float4*)&ar[0] = *(const float4*)&As[k][ty * TM];
            *(float4*)&ar[4] = *(const float4*)&As[k][ty * TM + 4];
            *(float4*)&br[0] = *(const float4*)&Bs[k][tx * TN];
            *(float4*)&br[4] = *(const float4*)&Bs[k][tx * TN + 4];
#pragma unroll
            for (int i = 0; i < TM; i++)
#pragma unroll
                for (int j = 0; j < TN; j++) acc[i][j] += ar[i] * br[j];
        }
        __syncthreads();
    }

#pragma unroll
    for (int i = 0; i < TM; i++) {
        int row = brow * BM + ty * TM + i;
#pragma unroll
        for (int j = 0; j < TN; j += 4) {
            int col = bcol * BN + tx * TN + j;
            float4 v;
            v.x = acc[i][j + 0]; v.y = acc[i][j + 1];
            v.z = acc[i][j + 2]; v.w = acc[i][j + 3];
            float4 bb = *(const float4*)(bias + col);
            v.x += bb.x; v.y += bb.y; v.z += bb.z; v.w += bb.w;
            if (EPI == 1) {
                v.x = 0.5f * v.x * (1.f + erff(v.x * 0.70710678118654752f));
                v.y = 0.5f * v.y * (1.f + erff(v.y * 0.70710678118654752f));
                v.z = 0.5f * v.z * (1.f + erff(v.z * 0.70710678118654752f));
                v.w = 0.5f * v.w * (1.f + erff(v.w * 0.70710678118654752f));
            }
            if (EPI == 2) {
                float4 rr = *(const float4*)(res + (size_t)row * N + col);
                v.x += rr.x; v.y += rr.y; v.z += rr.z; v.w += rr.w;
            }
            *(float4*)(C + (size_t)row * N + col) = v;
        }
    }
}

// ---------------- Flash attention: Q tile 64, K/V tile 64, online softmax ----
// grid (L/64, NH, B), 256 threads. Thread (qi = tid/4, l4 = tid%4) owns
// query row qi and output dims [l4*16, l4*16+16).
__global__ void __launch_bounds__(256, 2)
attn_kernel(const int* __restrict__ mask, float* __restrict__ O) {
    __shared__ float Ks[64][64];
    __shared__ float Vs[64][64];
    __shared__ float Ps[64][65];   // padded against bank conflicts
    __shared__ float mb[64];

    int tid = threadIdx.x;
    int qt = blockIdx.x, h = blockIdx.y, b = blockIdx.z;
    int qi = tid >> 2, l4 = tid & 3;
    int qrow = qt * 64 + qi;

    const float* qptr = g_qkv + ((size_t)(b * LSEQ + qrow)) * NQKV + h * HD;
    const float sc = 0.125f; // 1/sqrt(64)
    float4 qv[16];
#pragma unroll
    for (int i = 0; i < 16; i++) {
        float4 t = ((const float4*)qptr)[i];
        t.x *= sc; t.y *= sc; t.z *= sc; t.w *= sc;
        qv[i] = t;
    }

    float4 acc[4];
#pragma unroll
    for (int c = 0; c < 4; c++) acc[c] = make_float4(0.f, 0.f, 0.f, 0.f);
    float m = -1e30f, l = 0.f;

    for (int kt = 0; kt < LSEQ / 64; kt++) {
        __syncthreads();   // previous phase B done before overwriting tiles
        {
            int krow = kt * 64 + (tid >> 2);
            const float* kp = g_qkv + ((size_t)(b * LSEQ + krow)) * NQKV + DM + h * HD + l4 * 16;
            const float* vp = kp + DM;
#pragma unroll
            for (int c = 0; c < 4; c++) {
                *(float4*)&Ks[tid >> 2][l4 * 16 + c * 4] = ((const float4*)kp)[c];
                *(float4*)&Vs[tid >> 2][l4 * 16 + c * 4] = ((const float4*)vp)[c];
            }
            if (tid < 64) mb[tid] = mask[b * LSEQ + kt * 64 + tid] ? 0.f : -1e30f;
        }
        __syncthreads();

        // phase A: scores for keys [l4*16, l4*16+16)
        float p[16];
        float tmax = -1e30f;
#pragma unroll
        for (int kk = 0; kk < 16; kk++) {
            int key = l4 * 16 + kk;
            float4 d4 = make_float4(0.f, 0.f, 0.f, 0.f);
#pragma unroll
            for (int c = 0; c < 16; c++) {
                float4 kv4 = *(const float4*)&Ks[key][c * 4];
                d4.x += qv[c].x * kv4.x; d4.y += qv[c].y * kv4.y;
                d4.z += qv[c].z * kv4.z; d4.w += qv[c].w * kv4.w;
            }
            float s = (d4.x + d4.y) + (d4.z + d4.w) + mb[key];
            p[kk] = s;
            tmax = fmaxf(tmax, s);
        }
        tmax = fmaxf(tmax, __shfl_xor_sync(0xffffffffu, tmax, 1));
        tmax = fmaxf(tmax, __shfl_xor_sync(0xffffffffu, tmax, 2));
        float mnew  = fmaxf(m, tmax);
        float alpha = __expf(m - mnew);
        float ls = 0.f;
#pragma unroll
        for (int kk = 0; kk < 16; kk++) {
            float e = __expf(p[kk] - mnew);
            p[kk] = e;
            ls += e;
        }
        ls += __shfl_xor_sync(0xffffffffu, ls, 1);
        ls += __shfl_xor_sync(0xffffffffu, ls, 2);
        l = l * alpha + ls;
        m = mnew;
#pragma unroll
        for (int c = 0; c < 4; c++) {
            acc[c].x *= alpha; acc[c].y *= alpha;
            acc[c].z *= alpha; acc[c].w *= alpha;
        }
#pragma unroll
        for (int kk = 0; kk < 16; kk++) Ps[qi][l4 * 16 + kk] = p[kk];
        __syncthreads();

        // phase B: O += P @ V for our 16 dims
#pragma unroll 4
        for (int j = 0; j < 64; j++) {
            float pj = Ps[qi][j];
            const float* vrow = &Vs[j][l4 * 16];
#pragma unroll
            for (int c = 0; c < 4; c++) {
                float4 vv = *(const float4*)(vrow + c * 4);
                acc[c].x += pj * vv.x; acc[c].y += pj * vv.y;
                acc[c].z += pj * vv.z; acc[c].w += pj * vv.w;
            }
        }
    }

    float inv = 1.f / l;
    float* op = O + ((size_t)(b * LSEQ + qrow)) * DM + h * HD + l4 * 16;
#pragma unroll
    for (int c = 0; c < 4; c++) {
        float4 t = acc[c];
        t.x *= inv; t.y *= inv; t.z *= inv; t.w *= inv;
        ((float4*)op)[c] = t;
    }
}

// ---------------- launch ----------------
static float* symaddr(const void* sym) {
    void* p = nullptr;
    cudaGetSymbolAddress(&p, sym);
    return (float*)p;
}

extern "C" void kernel_launch(void* const* d_in, const int* in_sizes, int n_in,
                              void* d_out, int out_size) {
    (void)in_sizes; (void)n_in; (void)out_size;
    const float* x      = (const float*)d_in[0];
    const int*   mask   = (const int*)  d_in[1];
    const float* ln1_g  = (const float*)d_in[2];
    const float* ln1_b  = (const float*)d_in[3];
    const float* qkv_w  = (const float*)d_in[4];
    const float* qkv_b  = (const float*)d_in[5];
    const float* out_w  = (const float*)d_in[6];
    const float* out_b  = (const float*)d_in[7];
    const float* ln2_g  = (const float*)d_in[8];
    const float* ln2_b  = (const float*)d_in[9];
    const float* fc1_w  = (const float*)d_in[10];
    const float* fc1_b  = (const float*)d_in[11];
    const float* fc2_w  = (const float*)d_in[12];
    const float* fc2_b  = (const float*)d_in[13];
    float* out = (float*)d_out;

    float* p_h    = symaddr(g_h);
    float* p_qkv  = symaddr(g_qkv);
    float* p_attn = symaddr(g_attn);
    float* p_x1   = symaddr(g_x1);
    float* p_ffh  = symaddr(g_ffh);

    // 1. LN1
    ln_kernel<<<MROWS, 256>>>(x, ln1_g, ln1_b, p_h);
    // 2. QKV projection
    sgemm_kernel<0><<<dim3(NQKV / 128, MROWS / 128), 256>>>(
        p_h, qkv_w, qkv_b, nullptr, p_qkv, MROWS, NQKV, DM);
    // 3. attention
    attn_kernel<<<dim3(LSEQ / 64, NH, BB), 256>>>(mask, p_attn);
    // 4. output projection + residual
    sgemm_kernel<2><<<dim3(DM / 128, MROWS / 128), 256>>>(
        p_attn, out_w, out_b, x, p_x1, MROWS, DM, DM);
    // 5. LN2
    ln_kernel<<<MROWS, 256>>>(p_x1, ln2_g, ln2_b, p_h);
    // 6. fc1 + GELU
    sgemm_kernel<1><<<dim3(DFF / 128, MROWS / 128), 256>>>(
        p_h, fc1_w, fc1_b, nullptr, p_ffh, MROWS, DFF, DM);
    // 7. fc2 + residual -> output
    sgemm_kernel<2><<<dim3(DM / 128, MROWS / 128), 256>>>(
        p_ffh, fc2_w, fc2_b, p_x1, out, MROWS, DM, DFF);
}

// round 3
// speedup vs baseline: 3.3119x; 3.3119x over previous
#include <cuda_runtime.h>
#include <cuda_bf16.h>
#include <math.h>
#include <stdint.h>

// ---------------- problem constants ----------------
#define BB   2
#define LSEQ 2048
#define DM   768
#define NH   12
#define HD   64
#define DFF  3072
#define MROWS (BB*LSEQ)      // 4096
#define NQKV  (3*DM)         // 2304

// ---------------- scratch ----------------
__device__ float g_h   [MROWS*DM];
__device__ float g_qkv [MROWS*NQKV];
__device__ float g_attn[MROWS*DM];
__device__ float g_x1  [MROWS*DM];
__device__ float g_ffh [MROWS*DFF];

// ---------------- helpers ----------------
__device__ __forceinline__ uint32_t smem_u32(const void* p) {
    uint32_t a;
    asm("{ .reg .u64 t; cvta.to.shared.u64 t, %1; cvt.u32.u64 %0, t; }" : "=r"(a) : "l"(p));
    return a;
}
__device__ __forceinline__ uint32_t pack2(__nv_bfloat16 a, __nv_bfloat16 b) {
    uint32_t ua = (uint32_t)__bfloat16_as_ushort(a);
    uint32_t ub = (uint32_t)__bfloat16_as_ushort(b);
    return ua | (ub << 16);
}
__device__ __forceinline__ void ldsm_x4(uint32_t* r, uint32_t addr) {
    asm volatile("ldmatrix.sync.aligned.m8n8.x4.shared.b16 {%0,%1,%2,%3}, [%4];"
        : "=r"(r[0]), "=r"(r[1]), "=r"(r[2]), "=r"(r[3]) : "r"(addr));
}
__device__ __forceinline__ void ldsm_x4_t(uint32_t* r, uint32_t addr) {
    asm volatile("ldmatrix.sync.aligned.m8n8.x4.trans.shared.b16 {%0,%1,%2,%3}, [%4];"
        : "=r"(r[0]), "=r"(r[1]), "=r"(r[2]), "=r"(r[3]) : "r"(addr));
}
__device__ __forceinline__ void mma16816(float* d, const uint32_t* a, const uint32_t* b) {
    asm volatile("mma.sync.aligned.m16n8k16.row.col.f32.bf16.bf16.f32 "
        "{%0,%1,%2,%3}, {%4,%5,%6,%7}, {%8,%9}, {%0,%1,%2,%3};"
        : "+f"(d[0]), "+f"(d[1]), "+f"(d[2]), "+f"(d[3])
        : "r"(a[0]), "r"(a[1]), "r"(a[2]), "r"(a[3]), "r"(b[0]), "r"(b[1]));
}

// ---------------- LayerNorm ----------------
__global__ void ln_kernel(const float* __restrict__ X, const float* __restrict__ g,
                          const float* __restrict__ b, float* __restrict__ Y) {
    int row = blockIdx.x;
    const float* xr = X + (size_t)row * DM;
    float v[3];
    float s = 0.f, sq = 0.f;
#pragma unroll
    for (int i = 0; i < 3; i++) {
        v[i] = xr[threadIdx.x + i * 256];
        s += v[i]; sq += v[i] * v[i];
    }
#pragma unroll
    for (int o = 16; o > 0; o >>= 1) {
        s  += __shfl_xor_sync(0xffffffffu, s, o);
        sq += __shfl_xor_sync(0xffffffffu, sq, o);
    }
    __shared__ float red0[8], red1[8];
    int w = threadIdx.x >> 5, lane = threadIdx.x & 31;
    if (lane == 0) { red0[w] = s; red1[w] = sq; }
    __syncthreads();
    s = 0.f; sq = 0.f;
#pragma unroll
    for (int i = 0; i < 8; i++) { s += red0[i]; sq += red1[i]; }
    float mu  = s * (1.f / DM);
    float var = sq * (1.f / DM) - mu * mu;
    float inv = rsqrtf(var + 1e-5f);
    float* yr = Y + (size_t)row * DM;
#pragma unroll
    for (int i = 0; i < 3; i++) {
        int idx = threadIdx.x + i * 256;
        yr[idx] = (v[i] - mu) * inv * g[idx] + b[idx];
    }
}

// ---------------- HMMA GEMM: C = A @ W + bias (+epi) ----------------
// BM=128, BN=128, BK=32. 256 threads = 8 warps as 2(m)x4(n); warp tile 64x32.
// bf16 split: D = Ah@Wh + Ah@Wl + Al@Wh, fp32 register accumulators.
// Smem: A [128][32] bf16, row stride 80B (hi @0, lo @10240)
//       B [32][128] bf16, row stride 272B (hi @20480, lo @29184)
#define A_STRIDE 80
#define B_STRIDE 272
#define SM_A_HI 0
#define SM_A_LO 10240
#define SM_B_HI 20480
#define SM_B_LO 29184
#define SM_TOTAL 37888

template <int EPI>
__global__ void __launch_bounds__(256)
gemm_mma(const float* __restrict__ A, const float* __restrict__ W,
         const float* __restrict__ bias, const float* __restrict__ res,
         float* __restrict__ C, int M, int N, int K) {
    __shared__ char smem[SM_TOTAL];
    const uint32_t sb = smem_u32(smem);

    int tid = threadIdx.x, wid = tid >> 5, lane = tid & 31;
    int bn = blockIdx.x, bm = blockIdx.y;
    int wm = wid >> 2, wn = wid & 3;           // warp grid 2x4

    const float* Ab = A + (size_t)bm * 128 * K;
    const float* Wb = W + bn * 128;

    // gmem load mapping
    int a_c4 = tid & 7, a_r0 = tid >> 3;       // A: float4 col (k=a_c4*4), row a_r0 + p*32
    int b_n4 = tid & 31, b_k0 = tid >> 5;      // B: float4 col (n=b_n4*4), k row b_k0 + p*8

    // ldmatrix per-lane base offsets (bytes)
    uint32_t a_lm = (uint32_t)((wm * 64 + (lane & 7) + ((lane >> 3) & 1) * 8) * A_STRIDE
                               + ((lane >> 4) & 1) * 16);
    uint32_t b_lm = (uint32_t)(((lane & 7) + ((lane >> 3) & 1) * 8) * B_STRIDE
                               + (wn * 32 + (lane >> 4) * 8) * 2);

    float acc[4][4][4];
#pragma unroll
    for (int i = 0; i < 4; i++)
#pragma unroll
        for (int j = 0; j < 4; j++)
#pragma unroll
            for (int q = 0; q < 4; q++) acc[i][j][q] = 0.f;

    const int nkt = K / 32;
    float4 aReg[4], bReg[4];
    // prefetch tile 0
#pragma unroll
    for (int p = 0; p < 4; p++) {
        aReg[p] = *(const float4*)(Ab + (size_t)(a_r0 + p * 32) * K + a_c4 * 4);
        bReg[p] = *(const float4*)(Wb + (size_t)(b_k0 + p * 8) * N + b_n4 * 4);
    }

    for (int kt = 0; kt < nkt; kt++) {
        // store regs -> smem (split hi/lo)
#pragma unroll
        for (int p = 0; p < 4; p++) {
            float4 v = aReg[p];
            __nv_bfloat16 h0 = __float2bfloat16(v.x), h1 = __float2bfloat16(v.y);
            __nv_bfloat16 h2 = __float2bfloat16(v.z), h3 = __float2bfloat16(v.w);
            __nv_bfloat16 l0 = __float2bfloat16(v.x - __bfloat162float(h0));
            __nv_bfloat16 l1 = __float2bfloat16(v.y - __bfloat162float(h1));
            __nv_bfloat16 l2 = __float2bfloat16(v.z - __bfloat162float(h2));
            __nv_bfloat16 l3 = __float2bfloat16(v.w - __bfloat162float(h3));
            uint32_t off = (uint32_t)((a_r0 + p * 32) * A_STRIDE + a_c4 * 8);
            uint2 hp; hp.x = pack2(h0, h1); hp.y = pack2(h2, h3);
            uint2 lp; lp.x = pack2(l0, l1); lp.y = pack2(l2, l3);
            *(uint2*)(smem + SM_A_HI + off) = hp;
            *(uint2*)(smem + SM_A_LO + off) = lp;

            float4 u = bReg[p];
            __nv_bfloat16 g0 = __float2bfloat16(u.x), g1 = __float2bfloat16(u.y);
            __nv_bfloat16 g2 = __float2bfloat16(u.z), g3 = __float2bfloat16(u.w);
            __nv_bfloat16 m0 = __float2bfloat16(u.x - __bfloat162float(g0));
            __nv_bfloat16 m1 = __float2bfloat16(u.y - __bfloat162float(g1));
            __nv_bfloat16 m2 = __float2bfloat16(u.z - __bfloat162float(g2));
            __nv_bfloat16 m3 = __float2bfloat16(u.w - __bfloat162float(g3));
            uint32_t boff = (uint32_t)((b_k0 + p * 8) * B_STRIDE + b_n4 * 8);
            uint2 gp; gp.x = pack2(g0, g1); gp.y = pack2(g2, g3);
            uint2 mp; mp.x = pack2(m0, m1); mp.y = pack2(m2, m3);
            *(uint2*)(smem + SM_B_HI + boff) = gp;
            *(uint2*)(smem + SM_B_LO + boff) = mp;
        }
        __syncthreads();

        // prefetch next tile
        if (kt + 1 < nkt) {
#pragma unroll
            for (int p = 0; p < 4; p++) {
                aReg[p] = *(const float4*)(Ab + (size_t)(a_r0 + p * 32) * K + (kt + 1) * 32 + a_c4 * 4);
                bReg[p] = *(const float4*)(Wb + (size_t)((kt + 1) * 32 + b_k0 + p * 8) * N + b_n4 * 4);
            }
        }

        // compute 2 k-steps of 16
#pragma unroll
        for (int ks = 0; ks < 2; ks++) {
            uint32_t ah[4][4], al[4][4], bh[4][2], bl[4][2];
#pragma unroll
            for (int mt = 0; mt < 4; mt++) {
                uint32_t ao = a_lm + (uint32_t)(mt * 16 * A_STRIDE + ks * 32);
                ldsm_x4(ah[mt], sb + SM_A_HI + ao);
                ldsm_x4(al[mt], sb + SM_A_LO + ao);
            }
#pragma unroll
            for (int np = 0; np < 2; np++) {
                uint32_t bo = b_lm + (uint32_t)(ks * 16 * B_STRIDE + np * 32);
                uint32_t th[4], tl[4];
                ldsm_x4_t(th, sb + SM_B_HI + bo);
                ldsm_x4_t(tl, sb + SM_B_LO + bo);
                bh[np * 2][0] = th[0]; bh[np * 2][1] = th[1];
                bh[np * 2 + 1][0] = th[2]; bh[np * 2 + 1][1] = th[3];
                bl[np * 2][0] = tl[0]; bl[np * 2][1] = tl[1];
                bl[np * 2 + 1][0] = tl[2]; bl[np * 2 + 1][1] = tl[3];
            }
#pragma unroll
            for (int mt = 0; mt < 4; mt++)
#pragma unroll
                for (int nt = 0; nt < 4; nt++) {
                    mma16816(acc[mt][nt], ah[mt], bh[nt]);
                    mma16816(acc[mt][nt], ah[mt], bl[nt]);
                    mma16816(acc[mt][nt], al[mt], bh[nt]);
                }
        }
        __syncthreads();
    }

    // epilogue: acc[mt][nt] -> rows bm*128+wm*64+mt*16+lane/4 (+8), cols bn*128+wn*32+nt*8+(lane%4)*2
    int r0 = bm * 128 + wm * 64 + (lane >> 2);
    int c0 = bn * 128 + wn * 32 + (lane & 3) * 2;
#pragma unroll
    for (int mt = 0; mt < 4; mt++) {
#pragma unroll
        for (int nt = 0; nt < 4; nt++) {
            int col = c0 + nt * 8;
            float bb0 = bias[col], bb1 = bias[col + 1];
#pragma unroll
            for (int half = 0; half < 2; half++) {
                int row = r0 + mt * 16 + half * 8;
                float v0 = acc[mt][nt][half * 2 + 0] + bb0;
                float v1 = acc[mt][nt][half * 2 + 1] + bb1;
                if (EPI == 1) {
                    v0 = 0.5f * v0 * (1.f + erff(v0 * 0.70710678118654752f));
                    v1 = 0.5f * v1 * (1.f + erff(v1 * 0.70710678118654752f));
                }
                if (EPI == 2) {
                    const float* rp = res + (size_t)row * N + col;
                    v0 += rp[0]; v1 += rp[1];
                }
                float2 o; o.x = v0; o.y = v1;
                *(float2*)(C + (size_t)row * N + col) = o;
            }
        }
    }
}

// ---------------- Flash attention, conflict-free dim-chunk mapping ----------
__global__ void __launch_bounds__(256)
attn_kernel(const int* __restrict__ mask, float* __restrict__ O) {
    __shared__ float Ks[64][64];
    __shared__ float Vs[64][64];
    __shared__ float mb[64];

    int tid = threadIdx.x;
    int qt = blockIdx.x, h = blockIdx.y, b = blockIdx.z;
    int qg = tid >> 2, l4 = tid & 3;
    int qa = qt * 128 + qg;
    int qb = qa + 64;
    const float sc = 0.125f;

    float4 qva[4], qvb[4];
#pragma unroll
    for (int c = 0; c < 4; c++) {
        float4 t = *(const float4*)(g_qkv + (size_t)(b * LSEQ + qa) * NQKV + h * HD + c * 16 + l4 * 4);
        t.x *= sc; t.y *= sc; t.z *= sc; t.w *= sc; qva[c] = t;
        float4 u = *(const float4*)(g_qkv + (size_t)(b * LSEQ + qb) * NQKV + h * HD + c * 16 + l4 * 4);
        u.x *= sc; u.y *= sc; u.z *= sc; u.w *= sc; qvb[c] = u;
    }

    float4 acca[4], accb[4];
#pragma unroll
    for (int c = 0; c < 4; c++) { acca[c] = make_float4(0, 0, 0, 0); accb[c] = make_float4(0, 0, 0, 0); }
    float ma = -1e30f, la = 0.f, mb_ = -1e30f, lb = 0.f;

    for (int kt = 0; kt < LSEQ / 64; kt++) {
        __syncthreads();
        {
            int krow = kt * 64 + qg;
            const float* kp = g_qkv + (size_t)(b * LSEQ + krow) * NQKV + DM + h * HD + l4 * 16;
            const float* vp = kp + DM;
#pragma unroll
            for (int i = 0; i < 4; i++) {
                *(float4*)&Ks[qg][l4 * 16 + i * 4] = ((const float4*)kp)[i];
                *(float4*)&Vs[qg][l4 * 16 + i * 4] = ((const float4*)vp)[i];
            }
            if (tid < 64) mb[tid] = mask[b * LSEQ + kt * 64 + tid] ? 0.f : -1e30f;
        }
        __syncthreads();

#pragma unroll
        for (int chunk = 0; chunk < 4; chunk++) {
            float pa[16], pb[16];
#pragma unroll
            for (int kk = 0; kk < 16; kk++) {
                int key = chunk * 16 + kk;
                float da = 0.f, db = 0.f;
#pragma unroll
                for (int c = 0; c < 4; c++) {
                    float4 kv = *(const float4*)&Ks[key][c * 16 + l4 * 4];
                    da += qva[c].x * kv.x + qva[c].y * kv.y + qva[c].z * kv.z + qva[c].w * kv.w;
                    db += qvb[c].x * kv.x + qvb[c].y * kv.y + qvb[c].z * kv.z + qvb[c].w * kv.w;
                }
                da += __shfl_xor_sync(0xffffffffu, da, 1);
                da += __shfl_xor_sync(0xffffffffu, da, 2);
                db += __shfl_xor_sync(0xffffffffu, db, 1);
                db += __shfl_xor_sync(0xffffffffu, db, 2);
                float mk = mb[key];
                pa[kk] = da + mk;
                pb[kk] = db + mk;
            }
            float ca = -1e30f, cb = -1e30f;
#pragma unroll
            for (int kk = 0; kk < 16; kk++) { ca = fmaxf(ca, pa[kk]); cb = fmaxf(cb, pb[kk]); }
            float mna = fmaxf(ma, ca), mnb = fmaxf(mb_, cb);
            float ala = __expf(ma - mna), alb = __expf(mb_ - mnb);
            ma = mna; mb_ = mnb;
            float sa = 0.f, sbv = 0.f;
#pragma unroll
            for (int kk = 0; kk < 16; kk++) {
                float ea = __expf(pa[kk] - ma); pa[kk] = ea; sa += ea;
                float eb = __expf(pb[kk] - mb_); pb[kk] = eb; sbv += eb;
            }
            la = la * ala + sa;
            lb = lb * alb + sbv;
#pragma unroll
            for (int c = 0; c < 4; c++) {
                acca[c].x *= ala; acca[c].y *= ala; acca[c].z *= ala; acca[c].w *= ala;
                accb[c].x *= alb; accb[c].y *= alb; accb[c].z *= alb; accb[c].w *= alb;
            }
#pragma unroll
            for (int kk = 0; kk < 16; kk++) {
                int key = chunk * 16 + kk;
                float ea = pa[kk], eb = pb[kk];
#pragma unroll
                for (int c = 0; c < 4; c++) {
                    float4 vv = *(const float4*)&Vs[key][c * 16 + l4 * 4];
                    acca[c].x += ea * vv.x; acca[c].y += ea * vv.y; acca[c].z += ea * vv.z; acca[c].w += ea * vv.w;
                    accb[c].x += eb * vv.x; accb[c].y += eb * vv.y; accb[c].z += eb * vv.z; accb[c].w += eb * vv.w;
                }
            }
        }
    }

    float ia = 1.f / la, ib = 1.f / lb;
#pragma unroll
    for (int c = 0; c < 4; c++) {
        float4 t = acca[c];
        t.x *= ia; t.y *= ia; t.z *= ia; t.w *= ia;
        *(float4*)(O + (size_t)(b * LSEQ + qa) * DM + h * HD + c * 16 + l4 * 4) = t;
        float4 u = accb[c];
        u.x *= ib; u.y *= ib; u.z *= ib; u.w *= ib;
        *(float4*)(O + (size_t)(b * LSEQ + qb) * DM + h * HD + c * 16 + l4 * 4) = u;
    }
}

// ---------------- launch ----------------
static float* symaddr(const void* sym) {
    void* p = nullptr;
    cudaGetSymbolAddress(&p, sym);
    return (float*)p;
}

extern "C" void kernel_launch(void* const* d_in, const int* in_sizes, int n_in,
                              void* d_out, int out_size) {
    (void)in_sizes; (void)n_in; (void)out_size;
    const float* x      = (const float*)d_in[0];
    const int*   mask   = (const int*)  d_in[1];
    const float* ln1_g  = (const float*)d_in[2];
    const float* ln1_b  = (const float*)d_in[3];
    const float* qkv_w  = (const float*)d_in[4];
    const float* qkv_b  = (const float*)d_in[5];
    const float* out_w  = (const float*)d_in[6];
    const float* out_b  = (const float*)d_in[7];
    const float* ln2_g  = (const float*)d_in[8];
    const float* ln2_b  = (const float*)d_in[9];
    const float* fc1_w  = (const float*)d_in[10];
    const float* fc1_b  = (const float*)d_in[11];
    const float* fc2_w  = (const float*)d_in[12];
    const float* fc2_b  = (const float*)d_in[13];
    float* out = (float*)d_out;

    float* p_h    = symaddr(g_h);
    float* p_qkv  = symaddr(g_qkv);
    float* p_attn = symaddr(g_attn);
    float* p_x1   = symaddr(g_x1);
    float* p_ffh  = symaddr(g_ffh);

    // 1. LN1
    ln_kernel<<<MROWS, 256>>>(x, ln1_g, ln1_b, p_h);
    // 2. QKV projection
    gemm_mma<0><<<dim3(NQKV / 128, MROWS / 128), 256>>>(
        p_h, qkv_w, qkv_b, nullptr, p_qkv, MROWS, NQKV, DM);
    // 3. attention
    attn_kernel<<<dim3(LSEQ / 128, NH, BB), 256>>>(mask, p_attn);
    // 4. output projection + residual
    gemm_mma<2><<<dim3(DM / 128, MROWS / 128), 256>>>(
        p_attn, out_w, out_b, x, p_x1, MROWS, DM, DM);
    // 5. LN2
    ln_kernel<<<MROWS, 256>>>(p_x1, ln2_g, ln2_b, p_h);
    // 6. fc1 + GELU
    gemm_mma<1><<<dim3(DFF / 128, MROWS / 128), 256>>>(
        p_h, fc1_w, fc1_b, nullptr, p_ffh, MROWS, DFF, DM);
    // 7. fc2 + residual -> output
    gemm_mma<2><<<dim3(DM / 128, MROWS / 128), 256>>>(
        p_ffh, fc2_w, fc2_b, p_x1, out, MROWS, DM, DFF);
}

// round 4
// speedup vs baseline: 3.4009x; 1.0269x over previous
#include <cuda_runtime.h>
#include <cuda_bf16.h>
#include <math.h>
#include <stdint.h>

// ---------------- problem constants ----------------
#define BB   2
#define LSEQ 2048
#define DM   768
#define NH   12
#define HD   64
#define DFF  3072
#define MROWS (BB*LSEQ)      // 4096
#define NQKV  (3*DM)         // 2304

// ---------------- scratch ----------------
__device__ float g_qkv [MROWS*NQKV];
__device__ float g_x1  [MROWS*DM];
__device__ __nv_bfloat16 g_h_h [MROWS*DM],  g_h_l [MROWS*DM];
__device__ __nv_bfloat16 g_at_h[MROWS*DM],  g_at_l[MROWS*DM];
__device__ __nv_bfloat16 g_ff_h[MROWS*DFF], g_ff_l[MROWS*DFF];
__device__ __nv_bfloat16 g_wqkv_h[NQKV*DM], g_wqkv_l[NQKV*DM];
__device__ __nv_bfloat16 g_wout_h[DM*DM],   g_wout_l[DM*DM];
__device__ __nv_bfloat16 g_wfc1_h[DFF*DM],  g_wfc1_l[DFF*DM];
__device__ __nv_bfloat16 g_wfc2_h[DM*DFF],  g_wfc2_l[DM*DFF];

// ---------------- helpers ----------------
__device__ __forceinline__ uint32_t smem_u32(const void* p) {
    uint32_t a;
    asm("{ .reg .u64 t; cvta.to.shared.u64 t, %1; cvt.u32.u64 %0, t; }" : "=r"(a) : "l"(p));
    return a;
}
__device__ __forceinline__ void ldsm_x4(uint32_t* r, uint32_t addr) {
    asm volatile("ldmatrix.sync.aligned.m8n8.x4.shared.b16 {%0,%1,%2,%3}, [%4];"
        : "=r"(r[0]), "=r"(r[1]), "=r"(r[2]), "=r"(r[3]) : "r"(addr));
}
__device__ __forceinline__ void mma16816(float* d, const uint32_t* a, const uint32_t* b) {
    asm volatile("mma.sync.aligned.m16n8k16.row.col.f32.bf16.bf16.f32 "
        "{%0,%1,%2,%3}, {%4,%5,%6,%7}, {%8,%9}, {%0,%1,%2,%3};"
        : "+f"(d[0]), "+f"(d[1]), "+f"(d[2]), "+f"(d[3])
        : "r"(a[0]), "r"(a[1]), "r"(a[2]), "r"(a[3]), "r"(b[0]), "r"(b[1]));
}
__device__ __forceinline__ void cp16(uint32_t s, const void* g) {
    asm volatile("cp.async.cg.shared.global [%0], [%1], 16;" :: "r"(s), "l"(g));
}
#define CP_COMMIT() asm volatile("cp.async.commit_group;" ::: "memory")
#define CP_WAIT(n)  asm volatile("cp.async.wait_group %0;" :: "n"(n) : "memory")

__device__ __forceinline__ void split2(float v, __nv_bfloat16& h, __nv_bfloat16& l) {
    h = __float2bfloat16(v);
    l = __float2bfloat16(v - __bfloat162float(h));
}

// ---------------- weight transpose + split: W[K][N] -> WT[N][K] hi/lo ------
__global__ void wconv_kernel(const float* __restrict__ W,
                             __nv_bfloat16* __restrict__ Th, __nv_bfloat16* __restrict__ Tl,
                             int K, int N) {
    __shared__ float t[32][33];
    int n0 = blockIdx.x * 32, k0 = blockIdx.y * 32;
    int tx = threadIdx.x & 31, ty = threadIdx.x >> 5;
#pragma unroll
    for (int i = 0; i < 4; i++) {
        int k = ty + i * 8;
        t[k][tx] = W[(size_t)(k0 + k) * N + n0 + tx];
    }
    __syncthreads();
#pragma unroll
    for (int i = 0; i < 4; i++) {
        int nr = ty + i * 8;
        float v = t[tx][nr];
        __nv_bfloat16 h, l;
        split2(v, h, l);
        size_t o = (size_t)(n0 + nr) * K + k0 + tx;
        Th[o] = h; Tl[o] = l;
    }
}

// ---------------- LayerNorm -> bf16 hi/lo planes ----------------
__global__ void ln_kernel(const float* __restrict__ X, const float* __restrict__ g,
                          const float* __restrict__ b,
                          __nv_bfloat16* __restrict__ Yh, __nv_bfloat16* __restrict__ Yl) {
    int row = blockIdx.x;
    const float* xr = X + (size_t)row * DM;
    float v[3];
    float s = 0.f, sq = 0.f;
#pragma unroll
    for (int i = 0; i < 3; i++) {
        v[i] = xr[threadIdx.x + i * 256];
        s += v[i]; sq += v[i] * v[i];
    }
#pragma unroll
    for (int o = 16; o > 0; o >>= 1) {
        s  += __shfl_xor_sync(0xffffffffu, s, o);
        sq += __shfl_xor_sync(0xffffffffu, sq, o);
    }
    __shared__ float red0[8], red1[8];
    int w = threadIdx.x >> 5, lane = threadIdx.x & 31;
    if (lane == 0) { red0[w] = s; red1[w] = sq; }
    __syncthreads();
    s = 0.f; sq = 0.f;
#pragma unroll
    for (int i = 0; i < 8; i++) { s += red0[i]; sq += red1[i]; }
    float mu  = s * (1.f / DM);
    float var = sq * (1.f / DM) - mu * mu;
    float inv = rsqrtf(var + 1e-5f);
#pragma unroll
    for (int i = 0; i < 3; i++) {
        int idx = threadIdx.x + i * 256;
        float y = (v[i] - mu) * inv * g[idx] + b[idx];
        __nv_bfloat16 h, l;
        split2(y, h, l);
        size_t o = (size_t)row * DM + idx;
        Yh[o] = h; Yl[o] = l;
    }
}

// ---------------- HMMA GEMM on pre-split bf16 ----------------
// A hi/lo [M][K] bf16, B hi/lo [N][K] bf16 (K-major). BM=BN=128, BK=32.
// 8 warps 2(m)x4(n), warp tile 64x32, cp.async double-buffered.
// MODE 0: C=v fp32; MODE 1: gelu(v) -> Ch/Cl; MODE 2: C=v+res fp32.
#define A_ST 80
#define PLANE 10240            // 128 rows * 80B
#define STAGE 40960            // 4 planes
#define GSM (2 * STAGE)        // 81920

template <int MODE>
__global__ void __launch_bounds__(256, 2)
gemm_bf(const __nv_bfloat16* __restrict__ Ah, const __nv_bfloat16* __restrict__ Al,
        const __nv_bfloat16* __restrict__ Bh, const __nv_bfloat16* __restrict__ Bl,
        const float* __restrict__ bias, const float* __restrict__ res,
        float* __restrict__ C, __nv_bfloat16* __restrict__ Ch, __nv_bfloat16* __restrict__ Cl,
        int M, int N, int K) {
    extern __shared__ char smem[];
    const uint32_t sb = smem_u32(smem);

    int tid = threadIdx.x, wid = tid >> 5, lane = tid & 31;
    int bn = blockIdx.x, bm = blockIdx.y;
    int wm = wid >> 2, wn = wid & 3;

    // cp.async mapping: idx in [0,512): row=idx>>2, col16=idx&3 (16B units)
    int r_a = tid >> 2, c_a = tid & 3;

    // ldmatrix lane offsets
    uint32_t a_lm = (uint32_t)((wm * 64 + (lane & 15)) * A_ST + ((lane >> 4) & 1) * 16);
    uint32_t b_lm = (uint32_t)((wn * 32 + (lane & 15)) * A_ST + ((lane >> 4) & 1) * 16);

    float acc[4][4][4];
#pragma unroll
    for (int i = 0; i < 4; i++)
#pragma unroll
        for (int j = 0; j < 4; j++)
#pragma unroll
            for (int q = 0; q < 4; q++) acc[i][j][q] = 0.f;

    const int nkt = K / 32;

    // stage loader: 8 cp16 per thread (A hi/lo + B hi/lo, 2 chunks each)
    auto load_stage = [&](int kt, int buf) {
        uint32_t st = sb + buf * STAGE;
        const __nv_bfloat16* ga = Ah + (size_t)(bm * 128) * K + kt * 32;
        const __nv_bfloat16* gal = Al + (size_t)(bm * 128) * K + kt * 32;
        const __nv_bfloat16* gb = Bh + (size_t)(bn * 128) * K + kt * 32;
        const __nv_bfloat16* gbl = Bl + (size_t)(bn * 128) * K + kt * 32;
#pragma unroll
        for (int i = 0; i < 2; i++) {
            int row = r_a + i * 64;
            uint32_t so = (uint32_t)(row * A_ST + c_a * 16);
            cp16(st + so,                 ga  + (size_t)row * K + c_a * 8);
            cp16(st + PLANE + so,         gal + (size_t)row * K + c_a * 8);
            cp16(st + 2 * PLANE + so,     gb  + (size_t)row * K + c_a * 8);
            cp16(st + 3 * PLANE + so,     gbl + (size_t)row * K + c_a * 8);
        }
    };

    load_stage(0, 0);
    CP_COMMIT();

    for (int kt = 0; kt < nkt; kt++) {
        if (kt + 1 < nkt) {
            load_stage(kt + 1, (kt + 1) & 1);
            CP_COMMIT();
            CP_WAIT(1);
        } else {
            CP_WAIT(0);
        }
        __syncthreads();

        uint32_t st = sb + (kt & 1) * STAGE;
#pragma unroll
        for (int ks = 0; ks < 2; ks++) {
            uint32_t ah[4][4], al[4][4], bh[4][2], bl[4][2];
#pragma unroll
            for (int mt = 0; mt < 4; mt++) {
                uint32_t ao = a_lm + (uint32_t)(mt * 16 * A_ST + ks * 32);
                ldsm_x4(ah[mt], st + ao);
                ldsm_x4(al[mt], st + PLANE + ao);
            }
#pragma unroll
            for (int nt2 = 0; nt2 < 2; nt2++) {
                uint32_t bo = b_lm + (uint32_t)(nt2 * 16 * A_ST + ks * 32);
                uint32_t th[4], tl[4];
                ldsm_x4(th, st + 2 * PLANE + bo);
                ldsm_x4(tl, st + 3 * PLANE + bo);
                // frag for n-tile nt2*2:   {r0, r2}; nt2*2+1: {r1, r3}
                bh[nt2 * 2][0] = th[0]; bh[nt2 * 2][1] = th[2];
                bh[nt2 * 2 + 1][0] = th[1]; bh[nt2 * 2 + 1][1] = th[3];
                bl[nt2 * 2][0] = tl[0]; bl[nt2 * 2][1] = tl[2];
                bl[nt2 * 2 + 1][0] = tl[1]; bl[nt2 * 2 + 1][1] = tl[3];
            }
#pragma unroll
            for (int mt = 0; mt < 4; mt++)
#pragma unroll
                for (int nt = 0; nt < 4; nt++) {
                    mma16816(acc[mt][nt], ah[mt], bh[nt]);
                    mma16816(acc[mt][nt], ah[mt], bl[nt]);
                    mma16816(acc[mt][nt], al[mt], bh[nt]);
                }
        }
        __syncthreads();
    }

    // epilogue
    int r0 = bm * 128 + wm * 64 + (lane >> 2);
    int c0 = bn * 128 + wn * 32 + (lane & 3) * 2;
#pragma unroll
    for (int mt = 0; mt < 4; mt++) {
#pragma unroll
        for (int nt = 0; nt < 4; nt++) {
            int col = c0 + nt * 8;
            float bb0 = bias[col], bb1 = bias[col + 1];
#pragma unroll
            for (int half = 0; half < 2; half++) {
                int row = r0 + mt * 16 + half * 8;
                float v0 = acc[mt][nt][half * 2 + 0] + bb0;
                float v1 = acc[mt][nt][half * 2 + 1] + bb1;
                if (MODE == 1) {
                    v0 = 0.5f * v0 * (1.f + erff(v0 * 0.70710678118654752f));
                    v1 = 0.5f * v1 * (1.f + erff(v1 * 0.70710678118654752f));
                    __nv_bfloat16 h0, l0, h1, l1;
                    split2(v0, h0, l0); split2(v1, h1, l1);
                    size_t o = (size_t)row * N + col;
                    __nv_bfloat162 hp; hp.x = h0; hp.y = h1;
                    __nv_bfloat162 lp; lp.x = l0; lp.y = l1;
                    *(__nv_bfloat162*)(Ch + o) = hp;
                    *(__nv_bfloat162*)(Cl + o) = lp;
                } else {
                    if (MODE == 2) {
                        const float* rp = res + (size_t)row * N + col;
                        v0 += rp[0]; v1 += rp[1];
                    }
                    float2 o; o.x = v0; o.y = v1;
                    *(float2*)(C + (size_t)row * N + col) = o;
                }
            }
        }
    }
}

// ---------------- Flash attention (SIMT fp32, conflict-free) ----------------
__global__ void __launch_bounds__(256)
attn_kernel(const int* __restrict__ mask,
            __nv_bfloat16* __restrict__ Oh, __nv_bfloat16* __restrict__ Ol) {
    __shared__ float Ks[64][64];
    __shared__ float Vs[64][64];
    __shared__ float mb[64];

    int tid = threadIdx.x;
    int qt = blockIdx.x, h = blockIdx.y, b = blockIdx.z;
    int qg = tid >> 2, l4 = tid & 3;
    int qa = qt * 128 + qg;
    int qb = qa + 64;
    const float sc = 0.125f;

    float4 qva[4], qvb[4];
#pragma unroll
    for (int c = 0; c < 4; c++) {
        float4 t = *(const float4*)(g_qkv + (size_t)(b * LSEQ + qa) * NQKV + h * HD + c * 16 + l4 * 4);
        t.x *= sc; t.y *= sc; t.z *= sc; t.w *= sc; qva[c] = t;
        float4 u = *(const float4*)(g_qkv + (size_t)(b * LSEQ + qb) * NQKV + h * HD + c * 16 + l4 * 4);
        u.x *= sc; u.y *= sc; u.z *= sc; u.w *= sc; qvb[c] = u;
    }

    float4 acca[4], accb[4];
#pragma unroll
    for (int c = 0; c < 4; c++) { acca[c] = make_float4(0, 0, 0, 0); accb[c] = make_float4(0, 0, 0, 0); }
    float ma = -1e30f, la = 0.f, mb_ = -1e30f, lb = 0.f;

    for (int kt = 0; kt < LSEQ / 64; kt++) {
        __syncthreads();
        {
            int krow = kt * 64 + qg;
            const float* kp = g_qkv + (size_t)(b * LSEQ + krow) * NQKV + DM + h * HD + l4 * 16;
            const float* vp = kp + DM;
#pragma unroll
            for (int i = 0; i < 4; i++) {
                *(float4*)&Ks[qg][l4 * 16 + i * 4] = ((const float4*)kp)[i];
                *(float4*)&Vs[qg][l4 * 16 + i * 4] = ((const float4*)vp)[i];
            }
            if (tid < 64) mb[tid] = mask[b * LSEQ + kt * 64 + tid] ? 0.f : -1e30f;
        }
        __syncthreads();

#pragma unroll
        for (int chunk = 0; chunk < 4; chunk++) {
            float pa[16], pb[16];
#pragma unroll
            for (int kk = 0; kk < 16; kk++) {
                int key = chunk * 16 + kk;
                float da = 0.f, db = 0.f;
#pragma unroll
                for (int c = 0; c < 4; c++) {
                    float4 kv = *(const float4*)&Ks[key][c * 16 + l4 * 4];
                    da += qva[c].x * kv.x + qva[c].y * kv.y + qva[c].z * kv.z + qva[c].w * kv.w;
                    db += qvb[c].x * kv.x + qvb[c].y * kv.y + qvb[c].z * kv.z + qvb[c].w * kv.w;
                }
                da += __shfl_xor_sync(0xffffffffu, da, 1);
                da += __shfl_xor_sync(0xffffffffu, da, 2);
                db += __shfl_xor_sync(0xffffffffu, db, 1);
                db += __shfl_xor_sync(0xffffffffu, db, 2);
                float mk = mb[key];
                pa[kk] = da + mk;
                pb[kk] = db + mk;
            }
            float ca = -1e30f, cb = -1e30f;
#pragma unroll
            for (int kk = 0; kk < 16; kk++) { ca = fmaxf(ca, pa[kk]); cb = fmaxf(cb, pb[kk]); }
            float mna = fmaxf(ma, ca), mnb = fmaxf(mb_, cb);
            float ala = __expf(ma - mna), alb = __expf(mb_ - mnb);
            ma = mna; mb_ = mnb;
            float sa = 0.f, sbv = 0.f;
#pragma unroll
            for (int kk = 0; kk < 16; kk++) {
                float ea = __expf(pa[kk] - ma); pa[kk] = ea; sa += ea;
                float eb = __expf(pb[kk] - mb_); pb[kk] = eb; sbv += eb;
            }
            la = la * ala + sa;
            lb = lb * alb + sbv;
#pragma unroll
            for (int c = 0; c < 4; c++) {
                acca[c].x *= ala; acca[c].y *= ala; acca[c].z *= ala; acca[c].w *= ala;
                accb[c].x *= alb; accb[c].y *= alb; accb[c].z *= alb; accb[c].w *= alb;
            }
#pragma unroll
            for (int kk = 0; kk < 16; kk++) {
                int key = chunk * 16 + kk;
                float ea = pa[kk], eb = pb[kk];
#pragma unroll
                for (int c = 0; c < 4; c++) {
                    float4 vv = *(const float4*)&Vs[key][c * 16 + l4 * 4];
                    acca[c].x += ea * vv.x; acca[c].y += ea * vv.y; acca[c].z += ea * vv.z; acca[c].w += ea * vv.w;
                    accb[c].x += eb * vv.x; accb[c].y += eb * vv.y; accb[c].z += eb * vv.z; accb[c].w += eb * vv.w;
                }
            }
        }
    }

    float ia = 1.f / la, ib = 1.f / lb;
#pragma unroll
    for (int c = 0; c < 4; c++) {
        float va[4] = { acca[c].x * ia, acca[c].y * ia, acca[c].z * ia, acca[c].w * ia };
        float vb[4] = { accb[c].x * ib, accb[c].y * ib, accb[c].z * ib, accb[c].w * ib };
        __nv_bfloat16 ha[4], laa[4], hb[4], lbb[4];
#pragma unroll
        for (int j = 0; j < 4; j++) { split2(va[j], ha[j], laa[j]); split2(vb[j], hb[j], lbb[j]); }
        size_t oa = (size_t)(b * LSEQ + qa) * DM + h * HD + c * 16 + l4 * 4;
        size_t ob = (size_t)(b * LSEQ + qb) * DM + h * HD + c * 16 + l4 * 4;
        uint2 pha, pla, phb, plb;
        pha.x = ((uint32_t)__bfloat16_as_ushort(ha[0])) | ((uint32_t)__bfloat16_as_ushort(ha[1]) << 16);
        pha.y = ((uint32_t)__bfloat16_as_ushort(ha[2])) | ((uint32_t)__bfloat16_as_ushort(ha[3]) << 16);
        pla.x = ((uint32_t)__bfloat16_as_ushort(laa[0])) | ((uint32_t)__bfloat16_as_ushort(laa[1]) << 16);
        pla.y = ((uint32_t)__bfloat16_as_ushort(laa[2])) | ((uint32_t)__bfloat16_as_ushort(laa[3]) << 16);
        phb.x = ((uint32_t)__bfloat16_as_ushort(hb[0])) | ((uint32_t)__bfloat16_as_ushort(hb[1]) << 16);
        phb.y = ((uint32_t)__bfloat16_as_ushort(hb[2])) | ((uint32_t)__bfloat16_as_ushort(hb[3]) << 16);
        plb.x = ((uint32_t)__bfloat16_as_ushort(lbb[0])) | ((uint32_t)__bfloat16_as_ushort(lbb[1]) << 16);
        plb.y = ((uint32_t)__bfloat16_as_ushort(lbb[2])) | ((uint32_t)__bfloat16_as_ushort(lbb[3]) << 16);
        *(uint2*)(Oh + oa) = pha;
        *(uint2*)(Ol + oa) = pla;
        *(uint2*)(Oh + ob) = phb;
        *(uint2*)(Ol + ob) = plb;
    }
}

// ---------------- launch ----------------
template <typename T>
static T* symaddr(const void* sym) {
    void* p = nullptr;
    cudaGetSymbolAddress(&p, sym);
    return (T*)p;
}

extern "C" void kernel_launch(void* const* d_in, const int* in_sizes, int n_in,
                              void* d_out, int out_size) {
    (void)in_sizes; (void)n_in; (void)out_size;
    const float* x      = (const float*)d_in[0];
    const int*   mask   = (const int*)  d_in[1];
    const float* ln1_g  = (const float*)d_in[2];
    const float* ln1_b  = (const float*)d_in[3];
    const float* qkv_w  = (const float*)d_in[4];
    const float* qkv_b  = (const float*)d_in[5];
    const float* out_w  = (const float*)d_in[6];
    const float* out_b  = (const float*)d_in[7];
    const float* ln2_g  = (const float*)d_in[8];
    const float* ln2_b  = (const float*)d_in[9];
    const float* fc1_w  = (const float*)d_in[10];
    const float* fc1_b  = (const float*)d_in[11];
    const float* fc2_w  = (const float*)d_in[12];
    const float* fc2_b  = (const float*)d_in[13];
    float* out = (float*)d_out;

    float* p_qkv = symaddr<float>(g_qkv);
    float* p_x1  = symaddr<float>(g_x1);
    __nv_bfloat16* p_hh  = symaddr<__nv_bfloat16>(g_h_h);
    __nv_bfloat16* p_hl  = symaddr<__nv_bfloat16>(g_h_l);
    __nv_bfloat16* p_ath = symaddr<__nv_bfloat16>(g_at_h);
    __nv_bfloat16* p_atl = symaddr<__nv_bfloat16>(g_at_l);
    __nv_bfloat16* p_ffh = symaddr<__nv_bfloat16>(g_ff_h);
    __nv_bfloat16* p_ffl = symaddr<__nv_bfloat16>(g_ff_l);
    __nv_bfloat16* wq_h = symaddr<__nv_bfloat16>(g_wqkv_h), *wq_l = symaddr<__nv_bfloat16>(g_wqkv_l);
    __nv_bfloat16* wo_h = symaddr<__nv_bfloat16>(g_wout_h), *wo_l = symaddr<__nv_bfloat16>(g_wout_l);
    __nv_bfloat16* w1_h = symaddr<__nv_bfloat16>(g_wfc1_h), *w1_l = symaddr<__nv_bfloat16>(g_wfc1_l);
    __nv_bfloat16* w2_h = symaddr<__nv_bfloat16>(g_wfc2_h), *w2_l = symaddr<__nv_bfloat16>(g_wfc2_l);

    cudaFuncSetAttribute(gemm_bf<0>, cudaFuncAttributeMaxDynamicSharedMemorySize, GSM);
    cudaFuncSetAttribute(gemm_bf<1>, cudaFuncAttributeMaxDynamicSharedMemorySize, GSM);
    cudaFuncSetAttribute(gemm_bf<2>, cudaFuncAttributeMaxDynamicSharedMemorySize, GSM);

    // weight conversions (transpose + bf16 split)
    wconv_kernel<<<dim3(NQKV / 32, DM / 32), 256>>>(qkv_w, wq_h, wq_l, DM, NQKV);
    wconv_kernel<<<dim3(DM / 32, DM / 32), 256>>>(out_w, wo_h, wo_l, DM, DM);
    wconv_kernel<<<dim3(DFF / 32, DM / 32), 256>>>(fc1_w, w1_h, w1_l, DM, DFF);
    wconv_kernel<<<dim3(DM / 32, DFF / 32), 256>>>(fc2_w, w2_h, w2_l, DFF, DM);

    // 1. LN1 -> bf16 planes
    ln_kernel<<<MROWS, 256>>>(x, ln1_g, ln1_b, p_hh, p_hl);
    // 2. QKV projection -> fp32 qkv
    gemm_bf<0><<<dim3(NQKV / 128, MROWS / 128), 256, GSM>>>(
        p_hh, p_hl, wq_h, wq_l, qkv_b, nullptr, p_qkv, nullptr, nullptr, MROWS, NQKV, DM);
    // 3. attention -> bf16 planes
    attn_kernel<<<dim3(LSEQ / 128, NH, BB), 256>>>(mask, p_ath, p_atl);
    // 4. output projection + residual -> fp32 x1
    gemm_bf<2><<<dim3(DM / 128, MROWS / 128), 256, GSM>>>(
        p_ath, p_atl, wo_h, wo_l, out_b, x, p_x1, nullptr, nullptr, MROWS, DM, DM);
    // 5. LN2 -> bf16 planes
    ln_kernel<<<MROWS, 256>>>(p_x1, ln2_g, ln2_b, p_hh, p_hl);
    // 6. fc1 + GELU -> bf16 planes
    gemm_bf<1><<<dim3(DFF / 128, MROWS / 128), 256, GSM>>>(
        p_hh, p_hl, w1_h, w1_l, fc1_b, nullptr, nullptr, p_ffh, p_ffl, MROWS, DFF, DM);
    // 7. fc2 + residual -> output
    gemm_bf<2><<<dim3(DM / 128, MROWS / 128), 256, GSM>>>(
        p_ffh, p_ffl, w2_h, w2_l, fc2_b, p_x1, out, nullptr, nullptr, MROWS, DM, DFF);
}

// round 5
// speedup vs baseline: 5.9390x; 1.7463x over previous
#include <cuda_runtime.h>
#include <cuda_bf16.h>
#include <math.h>
#include <stdint.h>

// ---------------- problem constants ----------------
#define BB   2
#define LSEQ 2048
#define DM   768
#define NH   12
#define HD   64
#define DFF  3072
#define MROWS (BB*LSEQ)      // 4096
#define NQKV  (3*DM)         // 2304
#define PLANE_ELEMS (BB*NH*LSEQ*HD)   // 3145728

// ---------------- scratch ----------------
__device__ float g_x1  [MROWS*DM];
__device__ __nv_bfloat16 g_h_h [MROWS*DM],  g_h_l [MROWS*DM];
__device__ __nv_bfloat16 g_at_h[MROWS*DM],  g_at_l[MROWS*DM];
__device__ __nv_bfloat16 g_ff_h[MROWS*DFF], g_ff_l[MROWS*DFF];
__device__ __nv_bfloat16 g_qh[PLANE_ELEMS], g_ql[PLANE_ELEMS];
__device__ __nv_bfloat16 g_kh[PLANE_ELEMS], g_kl[PLANE_ELEMS];
__device__ __nv_bfloat16 g_vh[PLANE_ELEMS], g_vl[PLANE_ELEMS];
__device__ __nv_bfloat16 g_wqkv_h[NQKV*DM], g_wqkv_l[NQKV*DM];
__device__ __nv_bfloat16 g_wout_h[DM*DM],   g_wout_l[DM*DM];
__device__ __nv_bfloat16 g_wfc1_h[DFF*DM],  g_wfc1_l[DFF*DM];
__device__ __nv_bfloat16 g_wfc2_h[DM*DFF],  g_wfc2_l[DM*DFF];

// ---------------- helpers ----------------
__device__ __forceinline__ uint32_t smem_u32(const void* p) {
    uint32_t a;
    asm("{ .reg .u64 t; cvta.to.shared.u64 t, %1; cvt.u32.u64 %0, t; }" : "=r"(a) : "l"(p));
    return a;
}
__device__ __forceinline__ void ldsm_x4(uint32_t* r, uint32_t addr) {
    asm volatile("ldmatrix.sync.aligned.m8n8.x4.shared.b16 {%0,%1,%2,%3}, [%4];"
        : "=r"(r[0]), "=r"(r[1]), "=r"(r[2]), "=r"(r[3]) : "r"(addr));
}
__device__ __forceinline__ void ldsm_x4_t(uint32_t* r, uint32_t addr) {
    asm volatile("ldmatrix.sync.aligned.m8n8.x4.trans.shared.b16 {%0,%1,%2,%3}, [%4];"
        : "=r"(r[0]), "=r"(r[1]), "=r"(r[2]), "=r"(r[3]) : "r"(addr));
}
__device__ __forceinline__ void mma16816(float* d, const uint32_t* a, const uint32_t* b) {
    asm volatile("mma.sync.aligned.m16n8k16.row.col.f32.bf16.bf16.f32 "
        "{%0,%1,%2,%3}, {%4,%5,%6,%7}, {%8,%9}, {%0,%1,%2,%3};"
        : "+f"(d[0]), "+f"(d[1]), "+f"(d[2]), "+f"(d[3])
        : "r"(a[0]), "r"(a[1]), "r"(a[2]), "r"(a[3]), "r"(b[0]), "r"(b[1]));
}
__device__ __forceinline__ void mma2(float* d, const uint32_t* a, uint32_t b0, uint32_t b1) {
    asm volatile("mma.sync.aligned.m16n8k16.row.col.f32.bf16.bf16.f32 "
        "{%0,%1,%2,%3}, {%4,%5,%6,%7}, {%8,%9}, {%0,%1,%2,%3};"
        : "+f"(d[0]), "+f"(d[1]), "+f"(d[2]), "+f"(d[3])
        : "r"(a[0]), "r"(a[1]), "r"(a[2]), "r"(a[3]), "r"(b0), "r"(b1));
}
__device__ __forceinline__ void cp16(uint32_t s, const void* g) {
    asm volatile("cp.async.cg.shared.global [%0], [%1], 16;" :: "r"(s), "l"(g));
}
#define CP_COMMIT() asm volatile("cp.async.commit_group;" ::: "memory")
#define CP_WAIT(n)  asm volatile("cp.async.wait_group %0;" :: "n"(n) : "memory")

__device__ __forceinline__ void split2(float v, __nv_bfloat16& h, __nv_bfloat16& l) {
    h = __float2bfloat16(v);
    l = __float2bfloat16(v - __bfloat162float(h));
}
__device__ __forceinline__ uint32_t packf2(float lo, float hi) {
    uint32_t r;
    asm("cvt.rn.bf16x2.f32 %0, %1, %2;" : "=r"(r) : "f"(hi), "f"(lo));
    return r;
}

// ---------------- weight transpose + split: W[K][N] -> WT[N][K] hi/lo ------
__global__ void wconv_kernel(const float* __restrict__ W,
                             __nv_bfloat16* __restrict__ Th, __nv_bfloat16* __restrict__ Tl,
                             int K, int N) {
    __shared__ float t[32][33];
    int n0 = blockIdx.x * 32, k0 = blockIdx.y * 32;
    int tx = threadIdx.x & 31, ty = threadIdx.x >> 5;
#pragma unroll
    for (int i = 0; i < 4; i++) {
        int k = ty + i * 8;
        t[k][tx] = W[(size_t)(k0 + k) * N + n0 + tx];
    }
    __syncthreads();
#pragma unroll
    for (int i = 0; i < 4; i++) {
        int nr = ty + i * 8;
        float v = t[tx][nr];
        __nv_bfloat16 h, l;
        split2(v, h, l);
        size_t o = (size_t)(n0 + nr) * K + k0 + tx;
        Th[o] = h; Tl[o] = l;
    }
}

// ---------------- LayerNorm -> bf16 hi/lo planes ----------------
__global__ void ln_kernel(const float* __restrict__ X, const float* __restrict__ g,
                          const float* __restrict__ b,
                          __nv_bfloat16* __restrict__ Yh, __nv_bfloat16* __restrict__ Yl) {
    int row = blockIdx.x;
    const float* xr = X + (size_t)row * DM;
    float v[3];
    float s = 0.f, sq = 0.f;
#pragma unroll
    for (int i = 0; i < 3; i++) {
        v[i] = xr[threadIdx.x + i * 256];
        s += v[i]; sq += v[i] * v[i];
    }
#pragma unroll
    for (int o = 16; o > 0; o >>= 1) {
        s  += __shfl_xor_sync(0xffffffffu, s, o);
        sq += __shfl_xor_sync(0xffffffffu, sq, o);
    }
    __shared__ float red0[8], red1[8];
    int w = threadIdx.x >> 5, lane = threadIdx.x & 31;
    if (lane == 0) { red0[w] = s; red1[w] = sq; }
    __syncthreads();
    s = 0.f; sq = 0.f;
#pragma unroll
    for (int i = 0; i < 8; i++) { s += red0[i]; sq += red1[i]; }
    float mu  = s * (1.f / DM);
    float var = sq * (1.f / DM) - mu * mu;
    float inv = rsqrtf(var + 1e-5f);
#pragma unroll
    for (int i = 0; i < 3; i++) {
        int idx = threadIdx.x + i * 256;
        float y = (v[i] - mu) * inv * g[idx] + b[idx];
        __nv_bfloat16 h, l;
        split2(y, h, l);
        size_t o = (size_t)row * DM + idx;
        Yh[o] = h; Yl[o] = l;
    }
}

// ---------------- HMMA GEMM on pre-split bf16 ----------------
// MODE 1: gelu -> Ch/Cl planes; MODE 2: +res -> fp32 C; MODE 3: QKV split planes.
#define A_ST 80
#define PLANE 10240
#define STAGE 40960
#define GSM3 (3 * STAGE)       // 122880

template <int MODE>
__global__ void __launch_bounds__(256)
gemm_bf(const __nv_bfloat16* __restrict__ Ah, const __nv_bfloat16* __restrict__ Al,
        const __nv_bfloat16* __restrict__ Bh, const __nv_bfloat16* __restrict__ Bl,
        const float* __restrict__ bias, const float* __restrict__ res,
        float* __restrict__ C, __nv_bfloat16* __restrict__ Ch, __nv_bfloat16* __restrict__ Cl,
        int M, int N, int K) {
    extern __shared__ char smem[];
    const uint32_t sb = smem_u32(smem);

    int tid = threadIdx.x, wid = tid >> 5, lane = tid & 31;
    int bn = blockIdx.x, bm = blockIdx.y;
    int wm = wid >> 2, wn = wid & 3;

    int r_a = tid >> 2, c_a = tid & 3;
    uint32_t a_lm = (uint32_t)((wm * 64 + (lane & 15)) * A_ST + ((lane >> 4) & 1) * 16);
    uint32_t b_lm = (uint32_t)((wn * 32 + (lane & 15)) * A_ST + ((lane >> 4) & 1) * 16);

    float acc[4][4][4];
#pragma unroll
    for (int i = 0; i < 4; i++)
#pragma unroll
        for (int j = 0; j < 4; j++)
#pragma unroll
            for (int q = 0; q < 4; q++) acc[i][j][q] = 0.f;

    const int nkt = K / 32;

    auto load_stage = [&](int kt, int buf) {
        uint32_t st = sb + buf * STAGE;
        const __nv_bfloat16* ga  = Ah + (size_t)(bm * 128) * K + kt * 32;
        const __nv_bfloat16* gal = Al + (size_t)(bm * 128) * K + kt * 32;
        const __nv_bfloat16* gb  = Bh + (size_t)(bn * 128) * K + kt * 32;
        const __nv_bfloat16* gbl = Bl + (size_t)(bn * 128) * K + kt * 32;
#pragma unroll
        for (int i = 0; i < 2; i++) {
            int row = r_a + i * 64;
            uint32_t so = (uint32_t)(row * A_ST + c_a * 16);
            cp16(st + so,             ga  + (size_t)row * K + c_a * 8);
            cp16(st + PLANE + so,     gal + (size_t)row * K + c_a * 8);
            cp16(st + 2 * PLANE + so, gb  + (size_t)row * K + c_a * 8);
            cp16(st + 3 * PLANE + so, gbl + (size_t)row * K + c_a * 8);
        }
    };

    load_stage(0, 0); CP_COMMIT();
    load_stage(1, 1); CP_COMMIT();

    int buf = 0;
    for (int kt = 0; kt < nkt; kt++) {
        CP_WAIT(1);
        __syncthreads();
        if (kt + 2 < nkt) {
            int b2 = buf + 2; if (b2 >= 3) b2 -= 3;
            load_stage(kt + 2, b2);
            CP_COMMIT();
        }
        uint32_t st = sb + buf * STAGE;
#pragma unroll
        for (int ks = 0; ks < 2; ks++) {
            uint32_t ah[4][4], al[4][4], bh[4][2], bl[4][2];
#pragma unroll
            for (int mt = 0; mt < 4; mt++) {
                uint32_t ao = a_lm + (uint32_t)(mt * 16 * A_ST + ks * 32);
                ldsm_x4(ah[mt], st + ao);
                ldsm_x4(al[mt], st + PLANE + ao);
            }
#pragma unroll
            for (int nt2 = 0; nt2 < 2; nt2++) {
                uint32_t bo = b_lm + (uint32_t)(nt2 * 16 * A_ST + ks * 32);
                uint32_t th[4], tl[4];
                ldsm_x4(th, st + 2 * PLANE + bo);
                ldsm_x4(tl, st + 3 * PLANE + bo);
                bh[nt2 * 2][0] = th[0]; bh[nt2 * 2][1] = th[2];
                bh[nt2 * 2 + 1][0] = th[1]; bh[nt2 * 2 + 1][1] = th[3];
                bl[nt2 * 2][0] = tl[0]; bl[nt2 * 2][1] = tl[2];
                bl[nt2 * 2 + 1][0] = tl[1]; bl[nt2 * 2 + 1][1] = tl[3];
            }
#pragma unroll
            for (int mt = 0; mt < 4; mt++)
#pragma unroll
                for (int nt = 0; nt < 4; nt++) {
                    mma16816(acc[mt][nt], ah[mt], bh[nt]);
                    mma16816(acc[mt][nt], ah[mt], bl[nt]);
                    mma16816(acc[mt][nt], al[mt], bh[nt]);
                }
        }
        if (++buf == 3) buf = 0;
    }

    int r0 = bm * 128 + wm * 64 + (lane >> 2);
    int c0 = bn * 128 + wn * 32 + (lane & 3) * 2;
#pragma unroll
    for (int mt = 0; mt < 4; mt++) {
#pragma unroll
        for (int nt = 0; nt < 4; nt++) {
            int col = c0 + nt * 8;
            float bb0 = bias[col], bb1 = bias[col + 1];
#pragma unroll
            for (int half = 0; half < 2; half++) {
                int row = r0 + mt * 16 + half * 8;
                float v0 = acc[mt][nt][half * 2 + 0] + bb0;
                float v1 = acc[mt][nt][half * 2 + 1] + bb1;
                if (MODE == 1) {
                    v0 = 0.5f * v0 * (1.f + erff(v0 * 0.70710678118654752f));
                    v1 = 0.5f * v1 * (1.f + erff(v1 * 0.70710678118654752f));
                    __nv_bfloat16 h0, l0, h1, l1;
                    split2(v0, h0, l0); split2(v1, h1, l1);
                    size_t o = (size_t)row * N + col;
                    __nv_bfloat162 hp; hp.x = h0; hp.y = h1;
                    __nv_bfloat162 lp; lp.x = l0; lp.y = l1;
                    *(__nv_bfloat162*)(Ch + o) = hp;
                    *(__nv_bfloat162*)(Cl + o) = lp;
                } else if (MODE == 2) {
                    const float* rp = res + (size_t)row * N + col;
                    float2 o; o.x = v0 + rp[0]; o.y = v1 + rp[1];
                    *(float2*)(C + (size_t)row * N + col) = o;
                } else { // MODE 3: scatter into Q/K/V bf16 planes
                    int i3 = col / DM;
                    int rem = col - i3 * DM;
                    int h = rem >> 6, d = rem & 63;
                    int bb = row >> 11, l = row & 2047;
                    size_t idx = (((size_t)bb * NH + h) * LSEQ + l) * HD + d;
                    if (i3 == 0) { v0 *= 0.125f; v1 *= 0.125f; }
                    __nv_bfloat16 h0, l0, h1, l1;
                    split2(v0, h0, l0); split2(v1, h1, l1);
                    __nv_bfloat162 hp; hp.x = h0; hp.y = h1;
                    __nv_bfloat162 lp; lp.x = l0; lp.y = l1;
                    __nv_bfloat16* ph = (i3 == 0) ? g_qh : (i3 == 1) ? g_kh : g_vh;
                    __nv_bfloat16* pl = (i3 == 0) ? g_ql : (i3 == 1) ? g_kl : g_vl;
                    *(__nv_bfloat162*)(ph + idx) = hp;
                    *(__nv_bfloat162*)(pl + idx) = lp;
                }
            }
        }
    }
}

// ---------------- MMA flash attention ----------------
// 256 threads, Q tile 128 (16 rows/warp), K/V tile 64 double-buffered.
// QK: 3-term bf16 split; softmax fp32 in fragments; PV: bf16 P x (Vh+Vl).
#define AT_ST 144
#define AT_PLANE (64 * AT_ST)          // 9216
#define AT_STAGE (4 * AT_PLANE)        // 36864
#define AT_SMEM (2 * AT_STAGE + 512)   // 74240
#define NT_KV (LSEQ / 64)              // 32

__global__ void __launch_bounds__(256)
attn_mma(const int* __restrict__ mask,
         __nv_bfloat16* __restrict__ Oh, __nv_bfloat16* __restrict__ Ol) {
    extern __shared__ char sm[];
    const uint32_t sb = smem_u32(sm);
    float* mb2 = (float*)(sm + 2 * AT_STAGE);

    int tid = threadIdx.x, wid = tid >> 5, lane = tid & 31;
    int qt = blockIdx.x, h = blockIdx.y, b = blockIdx.z;
    size_t bh = ((size_t)b * NH + h) * LSEQ * HD;
    const __nv_bfloat16* Qh = g_qh + bh;
    const __nv_bfloat16* Ql = g_ql + bh;
    const __nv_bfloat16* Kh = g_kh + bh;
    const __nv_bfloat16* Kl = g_kl + bh;
    const __nv_bfloat16* Vh = g_vh + bh;
    const __nv_bfloat16* Vl = g_vl + bh;

    // ---- stage Q tile (128x64, hi+lo) into stage0, then to registers
    {
        int qrow0 = qt * 128;
#pragma unroll
        for (int i = 0; i < 4; i++) {
            int c = tid * 4 + i;
            int row = c >> 3, col = c & 7;
            cp16(sb + (uint32_t)(row * AT_ST + col * 16),
                 Qh + (size_t)(qrow0 + row) * HD + col * 8);
            cp16(sb + (uint32_t)(18432 + row * AT_ST + col * 16),
                 Ql + (size_t)(qrow0 + row) * HD + col * 8);
        }
    }
    CP_COMMIT();
    CP_WAIT(0);
    __syncthreads();

    uint32_t qfh[4][4], qfl[4][4];
    {
        uint32_t qbase = sb + (uint32_t)((wid * 16 + (lane & 15)) * AT_ST + (lane >> 4) * 16);
#pragma unroll
        for (int ks = 0; ks < 4; ks++) {
            ldsm_x4(qfh[ks], qbase + ks * 32);
            ldsm_x4(qfl[ks], qbase + 18432 + ks * 32);
        }
    }
    __syncthreads();

    auto load_kv = [&](int kt, int buf) {
        uint32_t st = sb + buf * AT_STAGE;
        const __nv_bfloat16* srcs[4] = {
            Kh + (size_t)kt * 64 * HD, Kl + (size_t)kt * 64 * HD,
            Vh + (size_t)kt * 64 * HD, Vl + (size_t)kt * 64 * HD };
#pragma unroll
        for (int p = 0; p < 4; p++)
#pragma unroll
            for (int i = 0; i < 2; i++) {
                int c = tid * 2 + i;
                int row = c >> 3, col = c & 7;
                cp16(st + (uint32_t)(p * AT_PLANE + row * AT_ST + col * 16),
                     srcs[p] + (size_t)row * HD + col * 8);
            }
    };

    if (tid < 64) mb2[tid] = mask[b * LSEQ + tid] ? 0.f : -1e30f;
    load_kv(0, 0);
    CP_COMMIT();

    float m0 = -1e30f, m1 = -1e30f, l0 = 0.f, l1 = 0.f;
    float o[8][4];
#pragma unroll
    for (int nt = 0; nt < 8; nt++)
#pragma unroll
        for (int q = 0; q < 4; q++) o[nt][q] = 0.f;

    for (int kt = 0; kt < NT_KV; kt++) {
        CP_WAIT(0);
        __syncthreads();
        if (kt + 1 < NT_KV) {
            if (tid < 64)
                mb2[((kt + 1) & 1) * 64 + tid] =
                    mask[b * LSEQ + (kt + 1) * 64 + tid] ? 0.f : -1e30f;
            load_kv(kt + 1, (kt + 1) & 1);
            CP_COMMIT();
        }
        uint32_t st = sb + (kt & 1) * AT_STAGE;
        const float* mrow = mb2 + (kt & 1) * 64;

        // ---- S = QK^T (3-term split)
        float s[8][4];
#pragma unroll
        for (int nt = 0; nt < 8; nt++)
#pragma unroll
            for (int q = 0; q < 4; q++) s[nt][q] = 0.f;

#pragma unroll
        for (int ks = 0; ks < 4; ks++) {
#pragma unroll
            for (int g = 0; g < 4; g++) {
                uint32_t addr = st + (uint32_t)((g * 16 + (lane & 15)) * AT_ST
                                                + ks * 32 + (lane >> 4) * 16);
                uint32_t t4[4], u4[4];
                ldsm_x4(t4, addr);
                ldsm_x4(u4, addr + AT_PLANE);
                mma2(s[g * 2], qfh[ks], t4[0], t4[2]);
                mma2(s[g * 2], qfh[ks], u4[0], u4[2]);
                mma2(s[g * 2], qfl[ks], t4[0], t4[2]);
                mma2(s[g * 2 + 1], qfh[ks], t4[1], t4[3]);
                mma2(s[g * 2 + 1], qfh[ks], u4[1], u4[3]);
                mma2(s[g * 2 + 1], qfl[ks], t4[1], t4[3]);
            }
        }

        // ---- mask + online softmax
        float rmax0 = -1e30f, rmax1 = -1e30f;
#pragma unroll
        for (int nt = 0; nt < 8; nt++) {
            int k0 = nt * 8 + (lane & 3) * 2;
            float mk0 = mrow[k0], mk1 = mrow[k0 + 1];
            s[nt][0] += mk0; s[nt][1] += mk1;
            s[nt][2] += mk0; s[nt][3] += mk1;
            rmax0 = fmaxf(rmax0, fmaxf(s[nt][0], s[nt][1]));
            rmax1 = fmaxf(rmax1, fmaxf(s[nt][2], s[nt][3]));
        }
        rmax0 = fmaxf(rmax0, __shfl_xor_sync(0xffffffffu, rmax0, 1));
        rmax0 = fmaxf(rmax0, __shfl_xor_sync(0xffffffffu, rmax0, 2));
        rmax1 = fmaxf(rmax1, __shfl_xor_sync(0xffffffffu, rmax1, 1));
        rmax1 = fmaxf(rmax1, __shfl_xor_sync(0xffffffffu, rmax1, 2));
        float mn0 = fmaxf(m0, rmax0), mn1 = fmaxf(m1, rmax1);
        float al0 = __expf(m0 - mn0), al1 = __expf(m1 - mn1);
        m0 = mn0; m1 = mn1;
        float ps0 = 0.f, ps1 = 0.f;
#pragma unroll
        for (int nt = 0; nt < 8; nt++) {
            s[nt][0] = __expf(s[nt][0] - m0);
            s[nt][1] = __expf(s[nt][1] - m0);
            s[nt][2] = __expf(s[nt][2] - m1);
            s[nt][3] = __expf(s[nt][3] - m1);
            ps0 += s[nt][0] + s[nt][1];
            ps1 += s[nt][2] + s[nt][3];
        }
        ps0 += __shfl_xor_sync(0xffffffffu, ps0, 1);
        ps0 += __shfl_xor_sync(0xffffffffu, ps0, 2);
        ps1 += __shfl_xor_sync(0xffffffffu, ps1, 1);
        ps1 += __shfl_xor_sync(0xffffffffu, ps1, 2);
        l0 = l0 * al0 + ps0;
        l1 = l1 * al1 + ps1;
#pragma unroll
        for (int nt = 0; nt < 8; nt++) {
            o[nt][0] *= al0; o[nt][1] *= al0;
            o[nt][2] *= al1; o[nt][3] *= al1;
        }

        // ---- P -> bf16 A-fragments
        uint32_t pf[4][4];
#pragma unroll
        for (int j = 0; j < 4; j++) {
            pf[j][0] = packf2(s[2 * j][0], s[2 * j][1]);
            pf[j][1] = packf2(s[2 * j][2], s[2 * j][3]);
            pf[j][2] = packf2(s[2 * j + 1][0], s[2 * j + 1][1]);
            pf[j][3] = packf2(s[2 * j + 1][2], s[2 * j + 1][3]);
        }

        // ---- O += P @ V (Vh + Vl via ldmatrix.trans)
        int g = lane >> 3;
#pragma unroll
        for (int j = 0; j < 4; j++) {
#pragma unroll
            for (int dt = 0; dt < 4; dt++) {
                uint32_t addr = st + (uint32_t)(2 * AT_PLANE
                    + (j * 16 + (g >> 1) * 8 + (lane & 7)) * AT_ST
                    + dt * 32 + (g & 1) * 16);
                uint32_t t4[4], u4[4];
                ldsm_x4_t(t4, addr);
                ldsm_x4_t(u4, addr + AT_PLANE);
                mma2(o[dt * 2], pf[j], t4[0], t4[2]);
                mma2(o[dt * 2], pf[j], u4[0], u4[2]);
                mma2(o[dt * 2 + 1], pf[j], t4[1], t4[3]);
                mma2(o[dt * 2 + 1], pf[j], u4[1], u4[3]);
            }
        }
    }

    // ---- finalize: O /= l, split to bf16 planes [row][DM]
    float i0 = 1.f / l0, i1 = 1.f / l1;
    int rowg = b * LSEQ + qt * 128 + wid * 16 + (lane >> 2);
#pragma unroll
    for (int nt = 0; nt < 8; nt++) {
        int col = h * HD + nt * 8 + (lane & 3) * 2;
        float v0 = o[nt][0] * i0, v1 = o[nt][1] * i0;
        float v2 = o[nt][2] * i1, v3 = o[nt][3] * i1;
        __nv_bfloat16 h0, lo0, h1, lo1, h2, lo2, h3, lo3;
        split2(v0, h0, lo0); split2(v1, h1, lo1);
        split2(v2, h2, lo2); split2(v3, h3, lo3);
        __nv_bfloat162 hp0; hp0.x = h0; hp0.y = h1;
        __nv_bfloat162 lp0; lp0.x = lo0; lp0.y = lo1;
        __nv_bfloat162 hp1; hp1.x = h2; hp1.y = h3;
        __nv_bfloat162 lp1; lp1.x = lo2; lp1.y = lo3;
        *(__nv_bfloat162*)(Oh + (size_t)rowg * DM + col) = hp0;
        *(__nv_bfloat162*)(Ol + (size_t)rowg * DM + col) = lp0;
        *(__nv_bfloat162*)(Oh + (size_t)(rowg + 8) * DM + col) = hp1;
        *(__nv_bfloat162*)(Ol + (size_t)(rowg + 8) * DM + col) = lp1;
    }
}

// ---------------- launch ----------------
template <typename T>
static T* symaddr(const void* sym) {
    void* p = nullptr;
    cudaGetSymbolAddress(&p, sym);
    return (T*)p;
}

extern "C" void kernel_launch(void* const* d_in, const int* in_sizes, int n_in,
                              void* d_out, int out_size) {
    (void)in_sizes; (void)n_in; (void)out_size;
    const float* x      = (const float*)d_in[0];
    const int*   mask   = (const int*)  d_in[1];
    const float* ln1_g  = (const float*)d_in[2];
    const float* ln1_b  = (const float*)d_in[3];
    const float* qkv_w  = (const float*)d_in[4];
    const float* qkv_b  = (const float*)d_in[5];
    const float* out_w  = (const float*)d_in[6];
    const float* out_b  = (const float*)d_in[7];
    const float* ln2_g  = (const float*)d_in[8];
    const float* ln2_b  = (const float*)d_in[9];
    const float* fc1_w  = (const float*)d_in[10];
    const float* fc1_b  = (const float*)d_in[11];
    const float* fc2_w  = (const float*)d_in[12];
    const float* fc2_b  = (const float*)d_in[13];
    float* out = (float*)d_out;

    float* p_x1  = symaddr<float>(g_x1);
    __nv_bfloat16* p_hh  = symaddr<__nv_bfloat16>(g_h_h);
    __nv_bfloat16* p_hl  = symaddr<__nv_bfloat16>(g_h_l);
    __nv_bfloat16* p_ath = symaddr<__nv_bfloat16>(g_at_h);
    __nv_bfloat16* p_atl = symaddr<__nv_bfloat16>(g_at_l);
    __nv_bfloat16* p_ffh = symaddr<__nv_bfloat16>(g_ff_h);
    __nv_bfloat16* p_ffl = symaddr<__nv_bfloat16>(g_ff_l);
    __nv_bfloat16* wq_h = symaddr<__nv_bfloat16>(g_wqkv_h), *wq_l = symaddr<__nv_bfloat16>(g_wqkv_l);
    __nv_bfloat16* wo_h = symaddr<__nv_bfloat16>(g_wout_h), *wo_l = symaddr<__nv_bfloat16>(g_wout_l);
    __nv_bfloat16* w1_h = symaddr<__nv_bfloat16>(g_wfc1_h), *w1_l = symaddr<__nv_bfloat16>(g_wfc1_l);
    __nv_bfloat16* w2_h = symaddr<__nv_bfloat16>(g_wfc2_h), *w2_l = symaddr<__nv_bfloat16>(g_wfc2_l);

    cudaFuncSetAttribute(gemm_bf<1>, cudaFuncAttributeMaxDynamicSharedMemorySize, GSM3);
    cudaFuncSetAttribute(gemm_bf<2>, cudaFuncAttributeMaxDynamicSharedMemorySize, GSM3);
    cudaFuncSetAttribute(gemm_bf<3>, cudaFuncAttributeMaxDynamicSharedMemorySize, GSM3);
    cudaFuncSetAttribute(attn_mma, cudaFuncAttributeMaxDynamicSharedMemorySize, AT_SMEM);

    // weight conversions
    wconv_kernel<<<dim3(NQKV / 32, DM / 32), 256>>>(qkv_w, wq_h, wq_l, DM, NQKV);
    wconv_kernel<<<dim3(DM / 32, DM / 32), 256>>>(out_w, wo_h, wo_l, DM, DM);
    wconv_kernel<<<dim3(DFF / 32, DM / 32), 256>>>(fc1_w, w1_h, w1_l, DM, DFF);
    wconv_kernel<<<dim3(DM / 32, DFF / 32), 256>>>(fc2_w, w2_h, w2_l, DFF, DM);

    // 1. LN1
    ln_kernel<<<MROWS, 256>>>(x, ln1_g, ln1_b, p_hh, p_hl);
    // 2. QKV projection -> Q/K/V bf16 hi/lo planes (Q pre-scaled)
    gemm_bf<3><<<dim3(NQKV / 128, MROWS / 128), 256, GSM3>>>(
        p_hh, p_hl, wq_h, wq_l, qkv_b, nullptr, nullptr, nullptr, nullptr, MROWS, NQKV, DM);
    // 3. MMA flash attention -> bf16 planes
    attn_mma<<<dim3(LSEQ / 128, NH, BB), 256, AT_SMEM>>>(mask, p_ath, p_atl);
    // 4. output projection + residual
    gemm_bf<2><<<dim3(DM / 128, MROWS / 128), 256, GSM3>>>(
        p_ath, p_atl, wo_h, wo_l, out_b, x, p_x1, nullptr, nullptr, MROWS, DM, DM);
    // 5. LN2
    ln_kernel<<<MROWS, 256>>>(p_x1, ln2_g, ln2_b, p_hh, p_hl);
    // 6. fc1 + GELU -> bf16 planes
    gemm_bf<1><<<dim3(DFF / 128, MROWS / 128), 256, GSM3>>>(
        p_hh, p_hl, w1_h, w1_l, fc1_b, nullptr, nullptr, p_ffh, p_ffl, MROWS, DFF, DM);
    // 7. fc2 + residual -> output
    gemm_bf<2><<<dim3(DM / 128, MROWS / 128), 256, GSM3>>>(
        p_ffh, p_ffl, w2_h, w2_l, fc2_b, p_x1, out, nullptr, nullptr, MROWS, DM, DFF);
}

// round 6
// speedup vs baseline: 6.4009x; 1.0778x over previous
#include <cuda_runtime.h>
#include <cuda_bf16.h>
#include <math.h>
#include <stdint.h>

// ---------------- problem constants ----------------
#define BB   2
#define LSEQ 2048
#define DM   768
#define NH   12
#define HD   64
#define DFF  3072
#define MROWS (BB*LSEQ)      // 4096
#define NQKV  (3*DM)         // 2304
#define PLANE_ELEMS (BB*NH*LSEQ*HD)   // 3145728

// ---------------- scratch ----------------
__device__ float g_x1  [MROWS*DM];
__device__ __nv_bfloat16 g_h_h [MROWS*DM],  g_h_l [MROWS*DM];
__device__ __nv_bfloat16 g_at_h[MROWS*DM],  g_at_l[MROWS*DM];
__device__ __nv_bfloat16 g_ff_h[MROWS*DFF], g_ff_l[MROWS*DFF];
__device__ __nv_bfloat16 g_qh[PLANE_ELEMS], g_ql[PLANE_ELEMS];
__device__ __nv_bfloat16 g_kh[PLANE_ELEMS], g_kl[PLANE_ELEMS];
__device__ __nv_bfloat16 g_vh[PLANE_ELEMS], g_vl[PLANE_ELEMS];
__device__ __nv_bfloat16 g_wqkv_h[NQKV*DM], g_wqkv_l[NQKV*DM];
__device__ __nv_bfloat16 g_wout_h[DM*DM],   g_wout_l[DM*DM];
__device__ __nv_bfloat16 g_wfc1_h[DFF*DM],  g_wfc1_l[DFF*DM];
__device__ __nv_bfloat16 g_wfc2_h[DM*DFF],  g_wfc2_l[DM*DFF];

// ---------------- helpers ----------------
__device__ __forceinline__ uint32_t smem_u32(const void* p) {
    uint32_t a;
    asm("{ .reg .u64 t; cvta.to.shared.u64 t, %1; cvt.u32.u64 %0, t; }" : "=r"(a) : "l"(p));
    return a;
}
__device__ __forceinline__ void ldsm_x4(uint32_t* r, uint32_t addr) {
    asm volatile("ldmatrix.sync.aligned.m8n8.x4.shared.b16 {%0,%1,%2,%3}, [%4];"
        : "=r"(r[0]), "=r"(r[1]), "=r"(r[2]), "=r"(r[3]) : "r"(addr));
}
__device__ __forceinline__ void ldsm_x4_t(uint32_t* r, uint32_t addr) {
    asm volatile("ldmatrix.sync.aligned.m8n8.x4.trans.shared.b16 {%0,%1,%2,%3}, [%4];"
        : "=r"(r[0]), "=r"(r[1]), "=r"(r[2]), "=r"(r[3]) : "r"(addr));
}
__device__ __forceinline__ void mma16816(float* d, const uint32_t* a, const uint32_t* b) {
    asm volatile("mma.sync.aligned.m16n8k16.row.col.f32.bf16.bf16.f32 "
        "{%0,%1,%2,%3}, {%4,%5,%6,%7}, {%8,%9}, {%0,%1,%2,%3};"
        : "+f"(d[0]), "+f"(d[1]), "+f"(d[2]), "+f"(d[3])
        : "r"(a[0]), "r"(a[1]), "r"(a[2]), "r"(a[3]), "r"(b[0]), "r"(b[1]));
}
__device__ __forceinline__ void mma2(float* d, const uint32_t* a, uint32_t b0, uint32_t b1) {
    asm volatile("mma.sync.aligned.m16n8k16.row.col.f32.bf16.bf16.f32 "
        "{%0,%1,%2,%3}, {%4,%5,%6,%7}, {%8,%9}, {%0,%1,%2,%3};"
        : "+f"(d[0]), "+f"(d[1]), "+f"(d[2]), "+f"(d[3])
        : "r"(a[0]), "r"(a[1]), "r"(a[2]), "r"(a[3]), "r"(b0), "r"(b1));
}
__device__ __forceinline__ void cp16(uint32_t s, const void* g) {
    asm volatile("cp.async.cg.shared.global [%0], [%1], 16;" :: "r"(s), "l"(g));
}
#define CP_COMMIT() asm volatile("cp.async.commit_group;" ::: "memory")
#define CP_WAIT(n)  asm volatile("cp.async.wait_group %0;" :: "n"(n) : "memory")

__device__ __forceinline__ void split2(float v, __nv_bfloat16& h, __nv_bfloat16& l) {
    h = __float2bfloat16(v);
    l = __float2bfloat16(v - __bfloat162float(h));
}
__device__ __forceinline__ uint32_t packf2(float lo, float hi) {
    uint32_t r;
    asm("cvt.rn.bf16x2.f32 %0, %1, %2;" : "=r"(r) : "f"(hi), "f"(lo));
    return r;
}

// ---------------- merged weight transpose + split ----------------
// tiles: qkv 72x24=1728 | out 24x24=576 | fc1 96x24=2304 | fc2 24x96=2304
__global__ void wconv_all(const float* __restrict__ qkv_w, const float* __restrict__ out_w,
                          const float* __restrict__ fc1_w, const float* __restrict__ fc2_w) {
    __shared__ float t[32][33];
    int bid = blockIdx.x;
    const float* W; __nv_bfloat16 *Th, *Tl; int K, N, tile;
    if (bid < 1728)      { W = qkv_w; Th = g_wqkv_h; Tl = g_wqkv_l; K = DM;  N = NQKV; tile = bid; }
    else if (bid < 2304) { W = out_w; Th = g_wout_h; Tl = g_wout_l; K = DM;  N = DM;   tile = bid - 1728; }
    else if (bid < 4608) { W = fc1_w; Th = g_wfc1_h; Tl = g_wfc1_l; K = DM;  N = DFF;  tile = bid - 2304; }
    else                 { W = fc2_w; Th = g_wfc2_h; Tl = g_wfc2_l; K = DFF; N = DM;   tile = bid - 4608; }
    int ntx = N / 32;
    int n0 = (tile % ntx) * 32, k0 = (tile / ntx) * 32;
    int tx = threadIdx.x & 31, ty = threadIdx.x >> 5;
#pragma unroll
    for (int i = 0; i < 4; i++) {
        int k = ty + i * 8;
        t[k][tx] = W[(size_t)(k0 + k) * N + n0 + tx];
    }
    __syncthreads();
#pragma unroll
    for (int i = 0; i < 4; i++) {
        int nr = ty + i * 8;
        float v = t[tx][nr];
        __nv_bfloat16 h, l;
        split2(v, h, l);
        size_t o = (size_t)(n0 + nr) * K + k0 + tx;
        Th[o] = h; Tl[o] = l;
    }
}

// ---------------- LayerNorm -> bf16 hi/lo planes ----------------
__global__ void ln_kernel(const float* __restrict__ X, const float* __restrict__ g,
                          const float* __restrict__ b,
                          __nv_bfloat16* __restrict__ Yh, __nv_bfloat16* __restrict__ Yl) {
    int row = blockIdx.x;
    const float* xr = X + (size_t)row * DM;
    float v[3];
    float s = 0.f, sq = 0.f;
#pragma unroll
    for (int i = 0; i < 3; i++) {
        v[i] = xr[threadIdx.x + i * 256];
        s += v[i]; sq += v[i] * v[i];
    }
#pragma unroll
    for (int o = 16; o > 0; o >>= 1) {
        s  += __shfl_xor_sync(0xffffffffu, s, o);
        sq += __shfl_xor_sync(0xffffffffu, sq, o);
    }
    __shared__ float red0[8], red1[8];
    int w = threadIdx.x >> 5, lane = threadIdx.x & 31;
    if (lane == 0) { red0[w] = s; red1[w] = sq; }
    __syncthreads();
    s = 0.f; sq = 0.f;
#pragma unroll
    for (int i = 0; i < 8; i++) { s += red0[i]; sq += red1[i]; }
    float mu  = s * (1.f / DM);
    float var = sq * (1.f / DM) - mu * mu;
    float inv = rsqrtf(var + 1e-5f);
#pragma unroll
    for (int i = 0; i < 3; i++) {
        int idx = threadIdx.x + i * 256;
        float y = (v[i] - mu) * inv * g[idx] + b[idx];
        __nv_bfloat16 h, l;
        split2(y, h, l);
        size_t o = (size_t)row * DM + idx;
        Yh[o] = h; Yl[o] = l;
    }
}

// ---------------- HMMA GEMM, BK=64, 3-stage ----------------
// MODE 1: gelu -> Ch/Cl planes; MODE 2: +res -> fp32 C; MODE 3: QKV split planes.
#define A_ST2 144
#define PLANE2 18432           // 128 * 144
#define STAGE2 73728           // 4 planes
#define GSM (3 * STAGE2)       // 221184

template <int MODE>
__global__ void __launch_bounds__(256)
gemm_bf(const __nv_bfloat16* __restrict__ Ah, const __nv_bfloat16* __restrict__ Al,
        const __nv_bfloat16* __restrict__ Bh, const __nv_bfloat16* __restrict__ Bl,
        const float* __restrict__ bias, const float* __restrict__ res,
        float* __restrict__ C, __nv_bfloat16* __restrict__ Ch, __nv_bfloat16* __restrict__ Cl,
        int M, int N, int K) {
    extern __shared__ char smem[];
    const uint32_t sb = smem_u32(smem);

    int tid = threadIdx.x, wid = tid >> 5, lane = tid & 31;
    int bn = blockIdx.x, bm = blockIdx.y;
    int wm = wid >> 2, wn = wid & 3;

    uint32_t a_lm = (uint32_t)((wm * 64 + (lane & 15)) * A_ST2 + ((lane >> 4) & 1) * 16);
    uint32_t b_lm = (uint32_t)((wn * 32 + (lane & 15)) * A_ST2 + ((lane >> 4) & 1) * 16);

    float acc[4][4][4];
#pragma unroll
    for (int i = 0; i < 4; i++)
#pragma unroll
        for (int j = 0; j < 4; j++)
#pragma unroll
            for (int q = 0; q < 4; q++) acc[i][j][q] = 0.f;

    const int nkt = K / 64;

    auto load_stage = [&](int kt, int buf) {
        uint32_t st = sb + buf * STAGE2;
        const __nv_bfloat16* srcs[4] = {
            Ah + (size_t)(bm * 128) * K + kt * 64,
            Al + (size_t)(bm * 128) * K + kt * 64,
            Bh + (size_t)(bn * 128) * K + kt * 64,
            Bl + (size_t)(bn * 128) * K + kt * 64 };
#pragma unroll
        for (int p = 0; p < 4; p++) {
#pragma unroll
            for (int i = 0; i < 4; i++) {
                int c = tid + i * 256;
                int row = c >> 3, col = c & 7;
                cp16(st + (uint32_t)(p * PLANE2 + row * A_ST2 + col * 16),
                     srcs[p] + (size_t)row * K + col * 8);
            }
        }
    };

    load_stage(0, 0); CP_COMMIT();
    if (nkt > 1) { load_stage(1, 1); CP_COMMIT(); }

    int buf = 0;
    for (int kt = 0; kt < nkt; kt++) {
        if (kt + 2 < nkt) { CP_WAIT(1); } else { CP_WAIT(0); }
        __syncthreads();
        if (kt + 2 < nkt) {
            int b2 = buf + 2; if (b2 >= 3) b2 -= 3;
            load_stage(kt + 2, b2);
            CP_COMMIT();
        }
        uint32_t st = sb + buf * STAGE2;
#pragma unroll
        for (int ks = 0; ks < 4; ks++) {
            uint32_t ah[4][4], al[4][4], bh[4][2], bl[4][2];
#pragma unroll
            for (int mt = 0; mt < 4; mt++) {
                uint32_t ao = a_lm + (uint32_t)(mt * 16 * A_ST2 + ks * 32);
                ldsm_x4(ah[mt], st + ao);
                ldsm_x4(al[mt], st + PLANE2 + ao);
            }
#pragma unroll
            for (int nt2 = 0; nt2 < 2; nt2++) {
                uint32_t bo = b_lm + (uint32_t)(nt2 * 16 * A_ST2 + ks * 32);
                uint32_t th[4], tl[4];
                ldsm_x4(th, st + 2 * PLANE2 + bo);
                ldsm_x4(tl, st + 3 * PLANE2 + bo);
                bh[nt2 * 2][0] = th[0]; bh[nt2 * 2][1] = th[2];
                bh[nt2 * 2 + 1][0] = th[1]; bh[nt2 * 2 + 1][1] = th[3];
                bl[nt2 * 2][0] = tl[0]; bl[nt2 * 2][1] = tl[2];
                bl[nt2 * 2 + 1][0] = tl[1]; bl[nt2 * 2 + 1][1] = tl[3];
            }
#pragma unroll
            for (int mt = 0; mt < 4; mt++)
#pragma unroll
                for (int nt = 0; nt < 4; nt++) {
                    mma16816(acc[mt][nt], ah[mt], bh[nt]);
                    mma16816(acc[mt][nt], ah[mt], bl[nt]);
                    mma16816(acc[mt][nt], al[mt], bh[nt]);
                }
        }
        if (++buf == 3) buf = 0;
    }

    int r0 = bm * 128 + wm * 64 + (lane >> 2);
    int c0 = bn * 128 + wn * 32 + (lane & 3) * 2;
#pragma unroll
    for (int mt = 0; mt < 4; mt++) {
#pragma unroll
        for (int nt = 0; nt < 4; nt++) {
            int col = c0 + nt * 8;
            float bb0 = bias[col], bb1 = bias[col + 1];
#pragma unroll
            for (int half = 0; half < 2; half++) {
                int row = r0 + mt * 16 + half * 8;
                float v0 = acc[mt][nt][half * 2 + 0] + bb0;
                float v1 = acc[mt][nt][half * 2 + 1] + bb1;
                if (MODE == 1) {
                    v0 = 0.5f * v0 * (1.f + erff(v0 * 0.70710678118654752f));
                    v1 = 0.5f * v1 * (1.f + erff(v1 * 0.70710678118654752f));
                    __nv_bfloat16 h0, l0, h1, l1;
                    split2(v0, h0, l0); split2(v1, h1, l1);
                    size_t o = (size_t)row * N + col;
                    __nv_bfloat162 hp; hp.x = h0; hp.y = h1;
                    __nv_bfloat162 lp; lp.x = l0; lp.y = l1;
                    *(__nv_bfloat162*)(Ch + o) = hp;
                    *(__nv_bfloat162*)(Cl + o) = lp;
                } else if (MODE == 2) {
                    const float* rp = res + (size_t)row * N + col;
                    float2 o; o.x = v0 + rp[0]; o.y = v1 + rp[1];
                    *(float2*)(C + (size_t)row * N + col) = o;
                } else { // MODE 3: scatter into Q/K/V bf16 planes
                    int i3 = col / DM;
                    int rem = col - i3 * DM;
                    int h = rem >> 6, d = rem & 63;
                    int bb = row >> 11, l = row & 2047;
                    size_t idx = (((size_t)bb * NH + h) * LSEQ + l) * HD + d;
                    if (i3 == 0) { v0 *= 0.125f; v1 *= 0.125f; }
                    __nv_bfloat16 h0, l0, h1, l1;
                    split2(v0, h0, l0); split2(v1, h1, l1);
                    __nv_bfloat162 hp; hp.x = h0; hp.y = h1;
                    __nv_bfloat162 lp; lp.x = l0; lp.y = l1;
                    __nv_bfloat16* ph = (i3 == 0) ? g_qh : (i3 == 1) ? g_kh : g_vh;
                    __nv_bfloat16* pl = (i3 == 0) ? g_ql : (i3 == 1) ? g_kl : g_vl;
                    *(__nv_bfloat162*)(ph + idx) = hp;
                    *(__nv_bfloat162*)(pl + idx) = lp;
                }
            }
        }
    }
}

// ---------------- MMA flash attention ----------------
#define AT_ST 144
#define AT_PLANE (64 * AT_ST)          // 9216
#define AT_STAGE (4 * AT_PLANE)        // 36864
#define AT_SMEM (2 * AT_STAGE + 512)   // 74240
#define NT_KV (LSEQ / 64)              // 32

__global__ void __launch_bounds__(256)
attn_mma(const int* __restrict__ mask,
         __nv_bfloat16* __restrict__ Oh, __nv_bfloat16* __restrict__ Ol) {
    extern __shared__ char sm[];
    const uint32_t sb = smem_u32(sm);
    float* mb2 = (float*)(sm + 2 * AT_STAGE);

    int tid = threadIdx.x, wid = tid >> 5, lane = tid & 31;
    int qt = blockIdx.x, h = blockIdx.y, b = blockIdx.z;
    size_t bh = ((size_t)b * NH + h) * LSEQ * HD;
    const __nv_bfloat16* Qh = g_qh + bh;
    const __nv_bfloat16* Ql = g_ql + bh;
    const __nv_bfloat16* Kh = g_kh + bh;
    const __nv_bfloat16* Kl = g_kl + bh;
    const __nv_bfloat16* Vh = g_vh + bh;
    const __nv_bfloat16* Vl = g_vl + bh;

    {
        int qrow0 = qt * 128;
#pragma unroll
        for (int i = 0; i < 4; i++) {
            int c = tid * 4 + i;
            int row = c >> 3, col = c & 7;
            cp16(sb + (uint32_t)(row * AT_ST + col * 16),
                 Qh + (size_t)(qrow0 + row) * HD + col * 8);
            cp16(sb + (uint32_t)(18432 + row * AT_ST + col * 16),
                 Ql + (size_t)(qrow0 + row) * HD + col * 8);
        }
    }
    CP_COMMIT();
    CP_WAIT(0);
    __syncthreads();

    uint32_t qfh[4][4], qfl[4][4];
    {
        uint32_t qbase = sb + (uint32_t)((wid * 16 + (lane & 15)) * AT_ST + (lane >> 4) * 16);
#pragma unroll
        for (int ks = 0; ks < 4; ks++) {
            ldsm_x4(qfh[ks], qbase + ks * 32);
            ldsm_x4(qfl[ks], qbase + 18432 + ks * 32);
        }
    }
    __syncthreads();

    auto load_kv = [&](int kt, int buf) {
        uint32_t st = sb + buf * AT_STAGE;
        const __nv_bfloat16* srcs[4] = {
            Kh + (size_t)kt * 64 * HD, Kl + (size_t)kt * 64 * HD,
            Vh + (size_t)kt * 64 * HD, Vl + (size_t)kt * 64 * HD };
#pragma unroll
        for (int p = 0; p < 4; p++)
#pragma unroll
            for (int i = 0; i < 2; i++) {
                int c = tid * 2 + i;
                int row = c >> 3, col = c & 7;
                cp16(st + (uint32_t)(p * AT_PLANE + row * AT_ST + col * 16),
                     srcs[p] + (size_t)row * HD + col * 8);
            }
    };

    if (tid < 64) mb2[tid] = mask[b * LSEQ + tid] ? 0.f : -1e30f;
    load_kv(0, 0);
    CP_COMMIT();

    float m0 = -1e30f, m1 = -1e30f, l0 = 0.f, l1 = 0.f;
    float o[8][4];
#pragma unroll
    for (int nt = 0; nt < 8; nt++)
#pragma unroll
        for (int q = 0; q < 4; q++) o[nt][q] = 0.f;

    for (int kt = 0; kt < NT_KV; kt++) {
        CP_WAIT(0);
        __syncthreads();
        if (kt + 1 < NT_KV) {
            if (tid < 64)
                mb2[((kt + 1) & 1) * 64 + tid] =
                    mask[b * LSEQ + (kt + 1) * 64 + tid] ? 0.f : -1e30f;
            load_kv(kt + 1, (kt + 1) & 1);
            CP_COMMIT();
        }
        uint32_t st = sb + (kt & 1) * AT_STAGE;
        const float* mrow = mb2 + (kt & 1) * 64;

        float s[8][4];
#pragma unroll
        for (int nt = 0; nt < 8; nt++)
#pragma unroll
            for (int q = 0; q < 4; q++) s[nt][q] = 0.f;

#pragma unroll
        for (int ks = 0; ks < 4; ks++) {
#pragma unroll
            for (int g = 0; g < 4; g++) {
                uint32_t addr = st + (uint32_t)((g * 16 + (lane & 15)) * AT_ST
                                                + ks * 32 + (lane >> 4) * 16);
                uint32_t t4[4], u4[4];
                ldsm_x4(t4, addr);
                ldsm_x4(u4, addr + AT_PLANE);
                mma2(s[g * 2], qfh[ks], t4[0], t4[2]);
                mma2(s[g * 2], qfh[ks], u4[0], u4[2]);
                mma2(s[g * 2], qfl[ks], t4[0], t4[2]);
                mma2(s[g * 2 + 1], qfh[ks], t4[1], t4[3]);
                mma2(s[g * 2 + 1], qfh[ks], u4[1], u4[3]);
                mma2(s[g * 2 + 1], qfl[ks], t4[1], t4[3]);
            }
        }

        float rmax0 = -1e30f, rmax1 = -1e30f;
#pragma unroll
        for (int nt = 0; nt < 8; nt++) {
            int k0 = nt * 8 + (lane & 3) * 2;
            float mk0 = mrow[k0], mk1 = mrow[k0 + 1];
            s[nt][0] += mk0; s[nt][1] += mk1;
            s[nt][2] += mk0; s[nt][3] += mk1;
            rmax0 = fmaxf(rmax0, fmaxf(s[nt][0], s[nt][1]));
            rmax1 = fmaxf(rmax1, fmaxf(s[nt][2], s[nt][3]));
        }
        rmax0 = fmaxf(rmax0, __shfl_xor_sync(0xffffffffu, rmax0, 1));
        rmax0 = fmaxf(rmax0, __shfl_xor_sync(0xffffffffu, rmax0, 2));
        rmax1 = fmaxf(rmax1, __shfl_xor_sync(0xffffffffu, rmax1, 1));
        rmax1 = fmaxf(rmax1, __shfl_xor_sync(0xffffffffu, rmax1, 2));
        float mn0 = fmaxf(m0, rmax0), mn1 = fmaxf(m1, rmax1);
        float al0 = __expf(m0 - mn0), al1 = __expf(m1 - mn1);
        m0 = mn0; m1 = mn1;
        float ps0 = 0.f, ps1 = 0.f;
#pragma unroll
        for (int nt = 0; nt < 8; nt++) {
            s[nt][0] = __expf(s[nt][0] - m0);
            s[nt][1] = __expf(s[nt][1] - m0);
            s[nt][2] = __expf(s[nt][2] - m1);
            s[nt][3] = __expf(s[nt][3] - m1);
            ps0 += s[nt][0] + s[nt][1];
            ps1 += s[nt][2] + s[nt][3];
        }
        ps0 += __shfl_xor_sync(0xffffffffu, ps0, 1);
        ps0 += __shfl_xor_sync(0xffffffffu, ps0, 2);
        ps1 += __shfl_xor_sync(0xffffffffu, ps1, 1);
        ps1 += __shfl_xor_sync(0xffffffffu, ps1, 2);
        l0 = l0 * al0 + ps0;
        l1 = l1 * al1 + ps1;
#pragma unroll
        for (int nt = 0; nt < 8; nt++) {
            o[nt][0] *= al0; o[nt][1] *= al0;
            o[nt][2] *= al1; o[nt][3] *= al1;
        }

        uint32_t pf[4][4];
#pragma unroll
        for (int j = 0; j < 4; j++) {
            pf[j][0] = packf2(s[2 * j][0], s[2 * j][1]);
            pf[j][1] = packf2(s[2 * j][2], s[2 * j][3]);
            pf[j][2] = packf2(s[2 * j + 1][0], s[2 * j + 1][1]);
            pf[j][3] = packf2(s[2 * j + 1][2], s[2 * j + 1][3]);
        }

        int g = lane >> 3;
#pragma unroll
        for (int j = 0; j < 4; j++) {
#pragma unroll
            for (int dt = 0; dt < 4; dt++) {
                uint32_t addr = st + (uint32_t)(2 * AT_PLANE
                    + (j * 16 + (g >> 1) * 8 + (lane & 7)) * AT_ST
                    + dt * 32 + (g & 1) * 16);
                uint32_t t4[4], u4[4];
                ldsm_x4_t(t4, addr);
                ldsm_x4_t(u4, addr + AT_PLANE);
                mma2(o[dt * 2], pf[j], t4[0], t4[2]);
                mma2(o[dt * 2], pf[j], u4[0], u4[2]);
                mma2(o[dt * 2 + 1], pf[j], t4[1], t4[3]);
                mma2(o[dt * 2 + 1], pf[j], u4[1], u4[3]);
            }
        }
    }

    float i0 = 1.f / l0, i1 = 1.f / l1;
    int rowg = b * LSEQ + qt * 128 + wid * 16 + (lane >> 2);
#pragma unroll
    for (int nt = 0; nt < 8; nt++) {
        int col = h * HD + nt * 8 + (lane & 3) * 2;
        float v0 = o[nt][0] * i0, v1 = o[nt][1] * i0;
        float v2 = o[nt][2] * i1, v3 = o[nt][3] * i1;
        __nv_bfloat16 h0, lo0, h1, lo1, h2, lo2, h3, lo3;
        split2(v0, h0, lo0); split2(v1, h1, lo1);
        split2(v2, h2, lo2); split2(v3, h3, lo3);
        __nv_bfloat162 hp0; hp0.x = h0; hp0.y = h1;
        __nv_bfloat162 lp0; lp0.x = lo0; lp0.y = lo1;
        __nv_bfloat162 hp1; hp1.x = h2; hp1.y = h3;
        __nv_bfloat162 lp1; lp1.x = lo2; lp1.y = lo3;
        *(__nv_bfloat162*)(Oh + (size_t)rowg * DM + col) = hp0;
        *(__nv_bfloat162*)(Ol + (size_t)rowg * DM + col) = lp0;
        *(__nv_bfloat162*)(Oh + (size_t)(rowg + 8) * DM + col) = hp1;
        *(__nv_bfloat162*)(Ol + (size_t)(rowg + 8) * DM + col) = lp1;
    }
}

// ---------------- launch ----------------
template <typename T>
static T* symaddr(const void* sym) {
    void* p = nullptr;
    cudaGetSymbolAddress(&p, sym);
    return (T*)p;
}

extern "C" void kernel_launch(void* const* d_in, const int* in_sizes, int n_in,
                              void* d_out, int out_size) {
    (void)in_sizes; (void)n_in; (void)out_size;
    const float* x      = (const float*)d_in[0];
    const int*   mask   = (const int*)  d_in[1];
    const float* ln1_g  = (const float*)d_in[2];
    const float* ln1_b  = (const float*)d_in[3];
    const float* qkv_w  = (const float*)d_in[4];
    const float* qkv_b  = (const float*)d_in[5];
    const float* out_w  = (const float*)d_in[6];
    const float* out_b  = (const float*)d_in[7];
    const float* ln2_g  = (const float*)d_in[8];
    const float* ln2_b  = (const float*)d_in[9];
    const float* fc1_w  = (const float*)d_in[10];
    const float* fc1_b  = (const float*)d_in[11];
    const float* fc2_w  = (const float*)d_in[12];
    const float* fc2_b  = (const float*)d_in[13];
    float* out = (float*)d_out;

    float* p_x1  = symaddr<float>(g_x1);
    __nv_bfloat16* p_hh  = symaddr<__nv_bfloat16>(g_h_h);
    __nv_bfloat16* p_hl  = symaddr<__nv_bfloat16>(g_h_l);
    __nv_bfloat16* p_ath = symaddr<__nv_bfloat16>(g_at_h);
    __nv_bfloat16* p_atl = symaddr<__nv_bfloat16>(g_at_l);
    __nv_bfloat16* p_ffh = symaddr<__nv_bfloat16>(g_ff_h);
    __nv_bfloat16* p_ffl = symaddr<__nv_bfloat16>(g_ff_l);
    __nv_bfloat16* wq_h = symaddr<__nv_bfloat16>(g_wqkv_h), *wq_l = symaddr<__nv_bfloat16>(g_wqkv_l);
    __nv_bfloat16* wo_h = symaddr<__nv_bfloat16>(g_wout_h), *wo_l = symaddr<__nv_bfloat16>(g_wout_l);
    __nv_bfloat16* w1_h = symaddr<__nv_bfloat16>(g_wfc1_h), *w1_l = symaddr<__nv_bfloat16>(g_wfc1_l);
    __nv_bfloat16* w2_h = symaddr<__nv_bfloat16>(g_wfc2_h), *w2_l = symaddr<__nv_bfloat16>(g_wfc2_l);

    cudaFuncSetAttribute(gemm_bf<1>, cudaFuncAttributeMaxDynamicSharedMemorySize, GSM);
    cudaFuncSetAttribute(gemm_bf<2>, cudaFuncAttributeMaxDynamicSharedMemorySize, GSM);
    cudaFuncSetAttribute(gemm_bf<3>, cudaFuncAttributeMaxDynamicSharedMemorySize, GSM);
    cudaFuncSetAttribute(attn_mma, cudaFuncAttributeMaxDynamicSharedMemorySize, AT_SMEM);

    // 1. LN1
    ln_kernel<<<MROWS, 256>>>(x, ln1_g, ln1_b, p_hh, p_hl);
    // 2. merged weight conversions
    wconv_all<<<6912, 256>>>(qkv_w, out_w, fc1_w, fc2_w);
    // 3. QKV projection -> Q/K/V bf16 hi/lo planes (Q pre-scaled)
    gemm_bf<3><<<dim3(NQKV / 128, MROWS / 128), 256, GSM>>>(
        p_hh, p_hl, wq_h, wq_l, qkv_b, nullptr, nullptr, nullptr, nullptr, MROWS, NQKV, DM);
    // 4. MMA flash attention -> bf16 planes
    attn_mma<<<dim3(LSEQ / 128, NH, BB), 256, AT_SMEM>>>(mask, p_ath, p_atl);
    // 5. output projection + residual
    gemm_bf<2><<<dim3(DM / 128, MROWS / 128), 256, GSM>>>(
        p_ath, p_atl, wo_h, wo_l, out_b, x, p_x1, nullptr, nullptr, MROWS, DM, DM);
    // 6. LN2
    ln_kernel<<<MROWS, 256>>>(p_x1, ln2_g, ln2_b, p_hh, p_hl);
    // 7. fc1 + GELU -> bf16 planes
    gemm_bf<1><<<dim3(DFF / 128, MROWS / 128), 256, GSM>>>(
        p_hh, p_hl, w1_h, w1_l, fc1_b, nullptr, nullptr, p_ffh, p_ffl, MROWS, DFF, DM);
    // 8. fc2 + residual -> output
    gemm_bf<2><<<dim3(DM / 128, MROWS / 128), 256, GSM>>>(
        p_ffh, p_ffl, w2_h, w2_l, fc2_b, p_x1, out, nullptr, nullptr, MROWS, DM, DFF);
}

// round 7
// speedup vs baseline: 6.7551x; 1.0553x over previous
#include <cuda_runtime.h>
#include <cuda_bf16.h>
#include <math.h>
#include <stdint.h>

// ---------------- problem constants ----------------
#define BB   2
#define LSEQ 2048
#define DM   768
#define NH   12
#define HD   64
#define DFF  3072
#define MROWS (BB*LSEQ)      // 4096
#define NQKV  (3*DM)         // 2304
#define PLANE_ELEMS (BB*NH*LSEQ*HD)   // 3145728

// ---------------- scratch ----------------
__device__ float g_x1  [MROWS*DM];
__device__ __nv_bfloat16 g_h_h [MROWS*DM],  g_h_l [MROWS*DM];
__device__ __nv_bfloat16 g_at_h[MROWS*DM],  g_at_l[MROWS*DM];
__device__ __nv_bfloat16 g_ff_h[MROWS*DFF], g_ff_l[MROWS*DFF];
__device__ __nv_bfloat16 g_qh[PLANE_ELEMS], g_ql[PLANE_ELEMS];
__device__ __nv_bfloat16 g_kh[PLANE_ELEMS], g_kl[PLANE_ELEMS];
__device__ __nv_bfloat16 g_vh[PLANE_ELEMS], g_vl[PLANE_ELEMS];
__device__ __nv_bfloat16 g_wqkv_h[NQKV*DM], g_wqkv_l[NQKV*DM];
__device__ __nv_bfloat16 g_wout_h[DM*DM],   g_wout_l[DM*DM];
__device__ __nv_bfloat16 g_wfc1_h[DFF*DM],  g_wfc1_l[DFF*DM];
__device__ __nv_bfloat16 g_wfc2_h[DM*DFF],  g_wfc2_l[DM*DFF];

// ---------------- helpers ----------------
__device__ __forceinline__ uint32_t smem_u32(const void* p) {
    uint32_t a;
    asm("{ .reg .u64 t; cvta.to.shared.u64 t, %1; cvt.u32.u64 %0, t; }" : "=r"(a) : "l"(p));
    return a;
}
__device__ __forceinline__ void ldsm_x4(uint32_t* r, uint32_t addr) {
    asm volatile("ldmatrix.sync.aligned.m8n8.x4.shared.b16 {%0,%1,%2,%3}, [%4];"
        : "=r"(r[0]), "=r"(r[1]), "=r"(r[2]), "=r"(r[3]) : "r"(addr));
}
__device__ __forceinline__ void ldsm_x4_t(uint32_t* r, uint32_t addr) {
    asm volatile("ldmatrix.sync.aligned.m8n8.x4.trans.shared.b16 {%0,%1,%2,%3}, [%4];"
        : "=r"(r[0]), "=r"(r[1]), "=r"(r[2]), "=r"(r[3]) : "r"(addr));
}
__device__ __forceinline__ void mma2(float* d, const uint32_t* a, uint32_t b0, uint32_t b1) {
    asm volatile("mma.sync.aligned.m16n8k16.row.col.f32.bf16.bf16.f32 "
        "{%0,%1,%2,%3}, {%4,%5,%6,%7}, {%8,%9}, {%0,%1,%2,%3};"
        : "+f"(d[0]), "+f"(d[1]), "+f"(d[2]), "+f"(d[3])
        : "r"(a[0]), "r"(a[1]), "r"(a[2]), "r"(a[3]), "r"(b0), "r"(b1));
}
__device__ __forceinline__ void cp16(uint32_t s, const void* g) {
    asm volatile("cp.async.cg.shared.global [%0], [%1], 16;" :: "r"(s), "l"(g));
}
#define CP_COMMIT() asm volatile("cp.async.commit_group;" ::: "memory")
#define CP_WAIT(n)  asm volatile("cp.async.wait_group %0;" :: "n"(n) : "memory")

__device__ __forceinline__ void split2(float v, __nv_bfloat16& h, __nv_bfloat16& l) {
    h = __float2bfloat16(v);
    l = __float2bfloat16(v - __bfloat162float(h));
}
__device__ __forceinline__ uint32_t packf2(float lo, float hi) {
    uint32_t r;
    asm("cvt.rn.bf16x2.f32 %0, %1, %2;" : "=r"(r) : "f"(hi), "f"(lo));
    return r;
}

// ---------------- merged weight transpose + split ----------------
__global__ void wconv_all(const float* __restrict__ qkv_w, const float* __restrict__ out_w,
                          const float* __restrict__ fc1_w, const float* __restrict__ fc2_w) {
    __shared__ float t[32][33];
    int bid = blockIdx.x;
    const float* W; __nv_bfloat16 *Th, *Tl; int K, N, tile;
    if (bid < 1728)      { W = qkv_w; Th = g_wqkv_h; Tl = g_wqkv_l; K = DM;  N = NQKV; tile = bid; }
    else if (bid < 2304) { W = out_w; Th = g_wout_h; Tl = g_wout_l; K = DM;  N = DM;   tile = bid - 1728; }
    else if (bid < 4608) { W = fc1_w; Th = g_wfc1_h; Tl = g_wfc1_l; K = DM;  N = DFF;  tile = bid - 2304; }
    else                 { W = fc2_w; Th = g_wfc2_h; Tl = g_wfc2_l; K = DFF; N = DM;   tile = bid - 4608; }
    int ntx = N / 32;
    int n0 = (tile % ntx) * 32, k0 = (tile / ntx) * 32;
    int tx = threadIdx.x & 31, ty = threadIdx.x >> 5;
#pragma unroll
    for (int i = 0; i < 4; i++) {
        int k = ty + i * 8;
        t[k][tx] = W[(size_t)(k0 + k) * N + n0 + tx];
    }
    __syncthreads();
#pragma unroll
    for (int i = 0; i < 4; i++) {
        int nr = ty + i * 8;
        float v = t[tx][nr];
        __nv_bfloat16 h, l;
        split2(v, h, l);
        size_t o = (size_t)(n0 + nr) * K + k0 + tx;
        Th[o] = h; Tl[o] = l;
    }
}

// ---------------- LayerNorm -> bf16 hi/lo planes ----------------
__global__ void ln_kernel(const float* __restrict__ X, const float* __restrict__ g,
                          const float* __restrict__ b,
                          __nv_bfloat16* __restrict__ Yh, __nv_bfloat16* __restrict__ Yl) {
    int row = blockIdx.x;
    const float* xr = X + (size_t)row * DM;
    float v[3];
    float s = 0.f, sq = 0.f;
#pragma unroll
    for (int i = 0; i < 3; i++) {
        v[i] = xr[threadIdx.x + i * 256];
        s += v[i]; sq += v[i] * v[i];
    }
#pragma unroll
    for (int o = 16; o > 0; o >>= 1) {
        s  += __shfl_xor_sync(0xffffffffu, s, o);
        sq += __shfl_xor_sync(0xffffffffu, sq, o);
    }
    __shared__ float red0[8], red1[8];
    int w = threadIdx.x >> 5, lane = threadIdx.x & 31;
    if (lane == 0) { red0[w] = s; red1[w] = sq; }
    __syncthreads();
    s = 0.f; sq = 0.f;
#pragma unroll
    for (int i = 0; i < 8; i++) { s += red0[i]; sq += red1[i]; }
    float mu  = s * (1.f / DM);
    float var = sq * (1.f / DM) - mu * mu;
    float inv = rsqrtf(var + 1e-5f);
#pragma unroll
    for (int i = 0; i < 3; i++) {
        int idx = threadIdx.x + i * 256;
        float y = (v[i] - mu) * inv * g[idx] + b[idx];
        __nv_bfloat16 h, l;
        split2(y, h, l);
        size_t o = (size_t)row * DM + idx;
        Yh[o] = h; Yl[o] = l;
    }
}

// ---------------- HMMA GEMM: BM=128, BN=64, BK=64, 2-stage, 2 CTAs/SM ------
#define A_ST2 144
#define APLANE 18432           // 128*144
#define BPLANE 9216            // 64*144
#define STG (2*APLANE + 2*BPLANE)   // 55296
#define GSM (2 * STG)               // 110592

template <int MODE>
__global__ void __launch_bounds__(256, 2)
gemm_bf(const __nv_bfloat16* __restrict__ Ah, const __nv_bfloat16* __restrict__ Al,
        const __nv_bfloat16* __restrict__ Bh, const __nv_bfloat16* __restrict__ Bl,
        const float* __restrict__ bias, const float* __restrict__ res,
        float* __restrict__ C, __nv_bfloat16* __restrict__ Ch, __nv_bfloat16* __restrict__ Cl,
        int M, int N, int K) {
    extern __shared__ char smem[];
    const uint32_t sb = smem_u32(smem);

    int tid = threadIdx.x, wid = tid >> 5, lane = tid & 31;
    int bn = blockIdx.x, bm = blockIdx.y;
    int wm = wid >> 2, wn = wid & 3;

    uint32_t a_lm = (uint32_t)((wm * 64 + (lane & 15)) * A_ST2 + ((lane >> 4) & 1) * 16);
    uint32_t b_lm = (uint32_t)((wn * 16 + (lane & 15)) * A_ST2 + ((lane >> 4) & 1) * 16);

    float acc[4][2][4];
#pragma unroll
    for (int i = 0; i < 4; i++)
#pragma unroll
        for (int j = 0; j < 2; j++)
#pragma unroll
            for (int q = 0; q < 4; q++) acc[i][j][q] = 0.f;

    const int nkt = K / 64;

    auto load_stage = [&](int kt, int buf) {
        uint32_t st = sb + buf * STG;
        const __nv_bfloat16* a0 = Ah + (size_t)(bm * 128) * K + kt * 64;
        const __nv_bfloat16* a1 = Al + (size_t)(bm * 128) * K + kt * 64;
        const __nv_bfloat16* b0 = Bh + (size_t)(bn * 64) * K + kt * 64;
        const __nv_bfloat16* b1 = Bl + (size_t)(bn * 64) * K + kt * 64;
#pragma unroll
        for (int i = 0; i < 4; i++) {       // A planes: 1024 chunks each
            int c = tid + i * 256;
            int row = c >> 3, col = c & 7;
            uint32_t so = (uint32_t)(row * A_ST2 + col * 16);
            cp16(st + so, a0 + (size_t)row * K + col * 8);
            cp16(st + APLANE + so, a1 + (size_t)row * K + col * 8);
        }
#pragma unroll
        for (int i = 0; i < 2; i++) {       // B planes: 512 chunks each
            int c = tid + i * 256;
            int row = c >> 3, col = c & 7;
            uint32_t so = (uint32_t)(row * A_ST2 + col * 16);
            cp16(st + 2 * APLANE + so, b0 + (size_t)row * K + col * 8);
            cp16(st + 2 * APLANE + BPLANE + so, b1 + (size_t)row * K + col * 8);
        }
    };

    load_stage(0, 0); CP_COMMIT();
    if (nkt > 1) { load_stage(1, 1); CP_COMMIT(); }

    for (int kt = 0; kt < nkt; kt++) {
        if (kt + 1 < nkt) { CP_WAIT(1); } else { CP_WAIT(0); }
        __syncthreads();
        uint32_t st = sb + (kt & 1) * STG;
#pragma unroll
        for (int ks = 0; ks < 4; ks++) {
            uint32_t ah[4][4], al[4][4], th[4], tl[4];
#pragma unroll
            for (int mt = 0; mt < 4; mt++) {
                uint32_t ao = a_lm + (uint32_t)(mt * 16 * A_ST2 + ks * 32);
                ldsm_x4(ah[mt], st + ao);
                ldsm_x4(al[mt], st + APLANE + ao);
            }
            uint32_t bo = b_lm + (uint32_t)(ks * 32);
            ldsm_x4(th, st + 2 * APLANE + bo);
            ldsm_x4(tl, st + 2 * APLANE + BPLANE + bo);
#pragma unroll
            for (int mt = 0; mt < 4; mt++) {
                mma2(acc[mt][0], ah[mt], th[0], th[2]);
                mma2(acc[mt][0], ah[mt], tl[0], tl[2]);
                mma2(acc[mt][0], al[mt], th[0], th[2]);
                mma2(acc[mt][1], ah[mt], th[1], th[3]);
                mma2(acc[mt][1], ah[mt], tl[1], tl[3]);
                mma2(acc[mt][1], al[mt], th[1], th[3]);
            }
        }
        __syncthreads();
        if (kt + 2 < nkt) {
            load_stage(kt + 2, kt & 1);
            CP_COMMIT();
        }
    }

    int r0 = bm * 128 + wm * 64 + (lane >> 2);
    int c0 = bn * 64 + wn * 16 + (lane & 3) * 2;
#pragma unroll
    for (int mt = 0; mt < 4; mt++) {
#pragma unroll
        for (int nt = 0; nt < 2; nt++) {
            int col = c0 + nt * 8;
            float bb0 = bias[col], bb1 = bias[col + 1];
#pragma unroll
            for (int half = 0; half < 2; half++) {
                int row = r0 + mt * 16 + half * 8;
                float v0 = acc[mt][nt][half * 2 + 0] + bb0;
                float v1 = acc[mt][nt][half * 2 + 1] + bb1;
                if (MODE == 1) {
                    v0 = 0.5f * v0 * (1.f + erff(v0 * 0.70710678118654752f));
                    v1 = 0.5f * v1 * (1.f + erff(v1 * 0.70710678118654752f));
                    __nv_bfloat16 h0, l0, h1, l1;
                    split2(v0, h0, l0); split2(v1, h1, l1);
                    size_t o = (size_t)row * N + col;
                    __nv_bfloat162 hp; hp.x = h0; hp.y = h1;
                    __nv_bfloat162 lp; lp.x = l0; lp.y = l1;
                    *(__nv_bfloat162*)(Ch + o) = hp;
                    *(__nv_bfloat162*)(Cl + o) = lp;
                } else if (MODE == 2) {
                    const float* rp = res + (size_t)row * N + col;
                    float2 o; o.x = v0 + rp[0]; o.y = v1 + rp[1];
                    *(float2*)(C + (size_t)row * N + col) = o;
                } else { // MODE 3: scatter into Q/K/V bf16 planes
                    int i3 = col / DM;
                    int rem = col - i3 * DM;
                    int h = rem >> 6, d = rem & 63;
                    int bb = row >> 11, l = row & 2047;
                    size_t idx = (((size_t)bb * NH + h) * LSEQ + l) * HD + d;
                    if (i3 == 0) { v0 *= 0.125f; v1 *= 0.125f; }
                    __nv_bfloat16 h0, l0, h1, l1;
                    split2(v0, h0, l0); split2(v1, h1, l1);
                    __nv_bfloat162 hp; hp.x = h0; hp.y = h1;
                    __nv_bfloat162 lp; lp.x = l0; lp.y = l1;
                    __nv_bfloat16* ph = (i3 == 0) ? g_qh : (i3 == 1) ? g_kh : g_vh;
                    __nv_bfloat16* pl = (i3 == 0) ? g_ql : (i3 == 1) ? g_kl : g_vl;
                    *(__nv_bfloat162*)(ph + idx) = hp;
                    *(__nv_bfloat162*)(pl + idx) = lp;
                }
            }
        }
    }
}

// ---------------- MMA flash attention: Q tile 64, 128 thr, 3 CTAs/SM -------
#define AT_ST 144
#define AT_PLANE (64 * AT_ST)          // 9216
#define AT_STAGE (4 * AT_PLANE)        // 36864
#define AT_SMEM (2 * AT_STAGE + 512)   // 74240
#define NT_KV (LSEQ / 64)              // 32

__global__ void __launch_bounds__(128, 3)
attn_mma(const int* __restrict__ mask,
         __nv_bfloat16* __restrict__ Oh, __nv_bfloat16* __restrict__ Ol) {
    extern __shared__ char sm[];
    const uint32_t sb = smem_u32(sm);
    float* mb2 = (float*)(sm + 2 * AT_STAGE);

    int tid = threadIdx.x, wid = tid >> 5, lane = tid & 31;
    int qt = blockIdx.x, h = blockIdx.y, b = blockIdx.z;
    size_t bh = ((size_t)b * NH + h) * LSEQ * HD;
    const __nv_bfloat16* Qh = g_qh + bh;
    const __nv_bfloat16* Ql = g_ql + bh;
    const __nv_bfloat16* Kh = g_kh + bh;
    const __nv_bfloat16* Kl = g_kl + bh;
    const __nv_bfloat16* Vh = g_vh + bh;
    const __nv_bfloat16* Vl = g_vl + bh;

    // ---- stage Q tile (64x64 hi/lo) into stage0, move to registers
    {
        int qrow0 = qt * 64;
#pragma unroll
        for (int i = 0; i < 4; i++) {
            int c = tid * 4 + i;
            int row = c >> 3, col = c & 7;
            cp16(sb + (uint32_t)(row * AT_ST + col * 16),
                 Qh + (size_t)(qrow0 + row) * HD + col * 8);
            cp16(sb + (uint32_t)(AT_PLANE + row * AT_ST + col * 16),
                 Ql + (size_t)(qrow0 + row) * HD + col * 8);
        }
    }
    CP_COMMIT();
    CP_WAIT(0);
    __syncthreads();

    uint32_t qfh[4][4], qfl[4][4];
    {
        uint32_t qbase = sb + (uint32_t)((wid * 16 + (lane & 15)) * AT_ST + (lane >> 4) * 16);
#pragma unroll
        for (int ks = 0; ks < 4; ks++) {
            ldsm_x4(qfh[ks], qbase + ks * 32);
            ldsm_x4(qfl[ks], qbase + AT_PLANE + ks * 32);
        }
    }
    __syncthreads();

    auto load_kv = [&](int kt, int buf) {
        uint32_t st = sb + buf * AT_STAGE;
        const __nv_bfloat16* srcs[4] = {
            Kh + (size_t)kt * 64 * HD, Kl + (size_t)kt * 64 * HD,
            Vh + (size_t)kt * 64 * HD, Vl + (size_t)kt * 64 * HD };
#pragma unroll
        for (int p = 0; p < 4; p++)
#pragma unroll
            for (int i = 0; i < 4; i++) {
                int c = tid * 4 + i;
                int row = c >> 3, col = c & 7;
                cp16(st + (uint32_t)(p * AT_PLANE + row * AT_ST + col * 16),
                     srcs[p] + (size_t)row * HD + col * 8);
            }
    };

    if (tid < 64) mb2[tid] = mask[b * LSEQ + tid] ? 0.f : -1e30f;
    load_kv(0, 0);
    CP_COMMIT();

    float m0 = -1e30f, m1 = -1e30f, l0 = 0.f, l1 = 0.f;
    float o[8][4];
#pragma unroll
    for (int nt = 0; nt < 8; nt++)
#pragma unroll
        for (int q = 0; q < 4; q++) o[nt][q] = 0.f;

    for (int kt = 0; kt < NT_KV; kt++) {
        CP_WAIT(0);
        __syncthreads();
        if (kt + 1 < NT_KV) {
            if (tid < 64)
                mb2[((kt + 1) & 1) * 64 + tid] =
                    mask[b * LSEQ + (kt + 1) * 64 + tid] ? 0.f : -1e30f;
            load_kv(kt + 1, (kt + 1) & 1);
            CP_COMMIT();
        }
        uint32_t st = sb + (kt & 1) * AT_STAGE;
        const float* mrow = mb2 + (kt & 1) * 64;

        float s[8][4];
#pragma unroll
        for (int nt = 0; nt < 8; nt++)
#pragma unroll
            for (int q = 0; q < 4; q++) s[nt][q] = 0.f;

#pragma unroll
        for (int ks = 0; ks < 4; ks++) {
#pragma unroll
            for (int g = 0; g < 4; g++) {
                uint32_t addr = st + (uint32_t)((g * 16 + (lane & 15)) * AT_ST
                                                + ks * 32 + (lane >> 4) * 16);
                uint32_t t4[4], u4[4];
                ldsm_x4(t4, addr);
                ldsm_x4(u4, addr + AT_PLANE);
                mma2(s[g * 2], qfh[ks], t4[0], t4[2]);
                mma2(s[g * 2], qfh[ks], u4[0], u4[2]);
                mma2(s[g * 2], qfl[ks], t4[0], t4[2]);
                mma2(s[g * 2 + 1], qfh[ks], t4[1], t4[3]);
                mma2(s[g * 2 + 1], qfh[ks], u4[1], u4[3]);
                mma2(s[g * 2 + 1], qfl[ks], t4[1], t4[3]);
            }
        }

        float rmax0 = -1e30f, rmax1 = -1e30f;
#pragma unroll
        for (int nt = 0; nt < 8; nt++) {
            int k0 = nt * 8 + (lane & 3) * 2;
            float mk0 = mrow[k0], mk1 = mrow[k0 + 1];
            s[nt][0] += mk0; s[nt][1] += mk1;
            s[nt][2] += mk0; s[nt][3] += mk1;
            rmax0 = fmaxf(rmax0, fmaxf(s[nt][0], s[nt][1]));
            rmax1 = fmaxf(rmax1, fmaxf(s[nt][2], s[nt][3]));
        }
        rmax0 = fmaxf(rmax0, __shfl_xor_sync(0xffffffffu, rmax0, 1));
        rmax0 = fmaxf(rmax0, __shfl_xor_sync(0xffffffffu, rmax0, 2));
        rmax1 = fmaxf(rmax1, __shfl_xor_sync(0xffffffffu, rmax1, 1));
        rmax1 = fmaxf(rmax1, __shfl_xor_sync(0xffffffffu, rmax1, 2));
        float mn0 = fmaxf(m0, rmax0), mn1 = fmaxf(m1, rmax1);
        float al0 = __expf(m0 - mn0), al1 = __expf(m1 - mn1);
        m0 = mn0; m1 = mn1;
        float ps0 = 0.f, ps1 = 0.f;
#pragma unroll
        for (int nt = 0; nt < 8; nt++) {
            s[nt][0] = __expf(s[nt][0] - m0);
            s[nt][1] = __expf(s[nt][1] - m0);
            s[nt][2] = __expf(s[nt][2] - m1);
            s[nt][3] = __expf(s[nt][3] - m1);
            ps0 += s[nt][0] + s[nt][1];
            ps1 += s[nt][2] + s[nt][3];
        }
        ps0 += __shfl_xor_sync(0xffffffffu, ps0, 1);
        ps0 += __shfl_xor_sync(0xffffffffu, ps0, 2);
        ps1 += __shfl_xor_sync(0xffffffffu, ps1, 1);
        ps1 += __shfl_xor_sync(0xffffffffu, ps1, 2);
        l0 = l0 * al0 + ps0;
        l1 = l1 * al1 + ps1;
#pragma unroll
        for (int nt = 0; nt < 8; nt++) {
            o[nt][0] *= al0; o[nt][1] *= al0;
            o[nt][2] *= al1; o[nt][3] *= al1;
        }

        uint32_t pf[4][4];
#pragma unroll
        for (int j = 0; j < 4; j++) {
            pf[j][0] = packf2(s[2 * j][0], s[2 * j][1]);
            pf[j][1] = packf2(s[2 * j][2], s[2 * j][3]);
            pf[j][2] = packf2(s[2 * j + 1][0], s[2 * j + 1][1]);
            pf[j][3] = packf2(s[2 * j + 1][2], s[2 * j + 1][3]);
        }

        int g = lane >> 3;
#pragma unroll
        for (int j = 0; j < 4; j++) {
#pragma unroll
            for (int dt = 0; dt < 4; dt++) {
                uint32_t addr = st + (uint32_t)(2 * AT_PLANE
                    + (j * 16 + (g >> 1) * 8 + (lane & 7)) * AT_ST
                    + dt * 32 + (g & 1) * 16);
                uint32_t t4[4], u4[4];
                ldsm_x4_t(t4, addr);
                ldsm_x4_t(u4, addr + AT_PLANE);
                mma2(o[dt * 2], pf[j], t4[0], t4[2]);
                mma2(o[dt * 2], pf[j], u4[0], u4[2]);
                mma2(o[dt * 2 + 1], pf[j], t4[1], t4[3]);
                mma2(o[dt * 2 + 1], pf[j], u4[1], u4[3]);
            }
        }
    }

    float i0 = 1.f / l0, i1 = 1.f / l1;
    int rowg = b * LSEQ + qt * 64 + wid * 16 + (lane >> 2);
#pragma unroll
    for (int nt = 0; nt < 8; nt++) {
        int col = h * HD + nt * 8 + (lane & 3) * 2;
        float v0 = o[nt][0] * i0, v1 = o[nt][1] * i0;
        float v2 = o[nt][2] * i1, v3 = o[nt][3] * i1;
        __nv_bfloat16 h0, lo0, h1, lo1, h2, lo2, h3, lo3;
        split2(v0, h0, lo0); split2(v1, h1, lo1);
        split2(v2, h2, lo2); split2(v3, h3, lo3);
        __nv_bfloat162 hp0; hp0.x = h0; hp0.y = h1;
        __nv_bfloat162 lp0; lp0.x = lo0; lp0.y = lo1;
        __nv_bfloat162 hp1; hp1.x = h2; hp1.y = h3;
        __nv_bfloat162 lp1; lp1.x = lo2; lp1.y = lo3;
        *(__nv_bfloat162*)(Oh + (size_t)rowg * DM + col) = hp0;
        *(__nv_bfloat162*)(Ol + (size_t)rowg * DM + col) = lp0;
        *(__nv_bfloat162*)(Oh + (size_t)(rowg + 8) * DM + col) = hp1;
        *(__nv_bfloat162*)(Ol + (size_t)(rowg + 8) * DM + col) = lp1;
    }
}

// ---------------- launch ----------------
template <typename T>
static T* symaddr(const void* sym) {
    void* p = nullptr;
    cudaGetSymbolAddress(&p, sym);
    return (T*)p;
}

extern "C" void kernel_launch(void* const* d_in, const int* in_sizes, int n_in,
                              void* d_out, int out_size) {
    (void)in_sizes; (void)n_in; (void)out_size;
    const float* x      = (const float*)d_in[0];
    const int*   mask   = (const int*)  d_in[1];
    const float* ln1_g  = (const float*)d_in[2];
    const float* ln1_b  = (const float*)d_in[3];
    const float* qkv_w  = (const float*)d_in[4];
    const float* qkv_b  = (const float*)d_in[5];
    const float* out_w  = (const float*)d_in[6];
    const float* out_b  = (const float*)d_in[7];
    const float* ln2_g  = (const float*)d_in[8];
    const float* ln2_b  = (const float*)d_in[9];
    const float* fc1_w  = (const float*)d_in[10];
    const float* fc1_b  = (const float*)d_in[11];
    const float* fc2_w  = (const float*)d_in[12];
    const float* fc2_b  = (const float*)d_in[13];
    float* out = (float*)d_out;

    float* p_x1  = symaddr<float>(g_x1);
    __nv_bfloat16* p_hh  = symaddr<__nv_bfloat16>(g_h_h);
    __nv_bfloat16* p_hl  = symaddr<__nv_bfloat16>(g_h_l);
    __nv_bfloat16* p_ath = symaddr<__nv_bfloat16>(g_at_h);
    __nv_bfloat16* p_atl = symaddr<__nv_bfloat16>(g_at_l);
    __nv_bfloat16* p_ffh = symaddr<__nv_bfloat16>(g_ff_h);
    __nv_bfloat16* p_ffl = symaddr<__nv_bfloat16>(g_ff_l);
    __nv_bfloat16* wq_h = symaddr<__nv_bfloat16>(g_wqkv_h), *wq_l = symaddr<__nv_bfloat16>(g_wqkv_l);
    __nv_bfloat16* wo_h = symaddr<__nv_bfloat16>(g_wout_h), *wo_l = symaddr<__nv_bfloat16>(g_wout_l);
    __nv_bfloat16* w1_h = symaddr<__nv_bfloat16>(g_wfc1_h), *w1_l = symaddr<__nv_bfloat16>(g_wfc1_l);
    __nv_bfloat16* w2_h = symaddr<__nv_bfloat16>(g_wfc2_h), *w2_l = symaddr<__nv_bfloat16>(g_wfc2_l);

    cudaFuncSetAttribute(gemm_bf<1>, cudaFuncAttributeMaxDynamicSharedMemorySize, GSM);
    cudaFuncSetAttribute(gemm_bf<2>, cudaFuncAttributeMaxDynamicSharedMemorySize, GSM);
    cudaFuncSetAttribute(gemm_bf<3>, cudaFuncAttributeMaxDynamicSharedMemorySize, GSM);
    cudaFuncSetAttribute(attn_mma, cudaFuncAttributeMaxDynamicSharedMemorySize, AT_SMEM);

    // 1. LN1
    ln_kernel<<<MROWS, 256>>>(x, ln1_g, ln1_b, p_hh, p_hl);
    // 2. merged weight conversions
    wconv_all<<<6912, 256>>>(qkv_w, out_w, fc1_w, fc2_w);
    // 3. QKV projection -> Q/K/V bf16 hi/lo planes (Q pre-scaled)
    gemm_bf<3><<<dim3(NQKV / 64, MROWS / 128), 256, GSM>>>(
        p_hh, p_hl, wq_h, wq_l, qkv_b, nullptr, nullptr, nullptr, nullptr, MROWS, NQKV, DM);
    // 4. MMA flash attention -> bf16 planes
    attn_mma<<<dim3(LSEQ / 64, NH, BB), 128, AT_SMEM>>>(mask, p_ath, p_atl);
    // 5. output projection + residual
    gemm_bf<2><<<dim3(DM / 64, MROWS / 128), 256, GSM>>>(
        p_ath, p_atl, wo_h, wo_l, out_b, x, p_x1, nullptr, nullptr, MROWS, DM, DM);
    // 6. LN2
    ln_kernel<<<MROWS, 256>>>(p_x1, ln2_g, ln2_b, p_hh, p_hl);
    // 7. fc1 + GELU -> bf16 planes
    gemm_bf<1><<<dim3(DFF / 64, MROWS / 128), 256, GSM>>>(
        p_hh, p_hl, w1_h, w1_l, fc1_b, nullptr, nullptr, p_ffh, p_ffl, MROWS, DFF, DM);
    // 8. fc2 + residual -> output
    gemm_bf<2><<<dim3(DM / 64, MROWS / 128), 256, GSM>>>(
        p_ffh, p_ffl, w2_h, w2_l, fc2_b, p_x1, out, nullptr, nullptr, MROWS, DM, DFF);
}

// round 8
// speedup vs baseline: 8.3816x; 1.2408x over previous
#include <cuda_runtime.h>
#include <cuda_bf16.h>
#include <math.h>
#include <stdint.h>

// ---------------- problem constants ----------------
#define BB   2
#define LSEQ 2048
#define DM   768
#define NH   12
#define HD   64
#define DFF  3072
#define MROWS (BB*LSEQ)      // 4096
#define NQKV  (3*DM)         // 2304
#define PLANE_ELEMS (BB*NH*LSEQ*HD)   // 3145728

// ---------------- scratch ----------------
__device__ float g_x1  [MROWS*DM];
__device__ __nv_bfloat16 g_h_h [MROWS*DM],  g_h_l [MROWS*DM];
__device__ __nv_bfloat16 g_at_h[MROWS*DM],  g_at_l[MROWS*DM];
__device__ __nv_bfloat16 g_ff_h[MROWS*DFF], g_ff_l[MROWS*DFF];
__device__ __nv_bfloat16 g_qh[PLANE_ELEMS];
__device__ __nv_bfloat16 g_kh[PLANE_ELEMS];
__device__ __nv_bfloat16 g_vh[PLANE_ELEMS];
__device__ __nv_bfloat16 g_wqkv_h[NQKV*DM], g_wqkv_l[NQKV*DM];
__device__ __nv_bfloat16 g_wout_h[DM*DM],   g_wout_l[DM*DM];
__device__ __nv_bfloat16 g_wfc1_h[DFF*DM],  g_wfc1_l[DFF*DM];
__device__ __nv_bfloat16 g_wfc2_h[DM*DFF],  g_wfc2_l[DM*DFF];

// ---------------- helpers ----------------
__device__ __forceinline__ uint32_t smem_u32(const void* p) {
    uint32_t a;
    asm("{ .reg .u64 t; cvta.to.shared.u64 t, %1; cvt.u32.u64 %0, t; }" : "=r"(a) : "l"(p));
    return a;
}
__device__ __forceinline__ void ldsm_x4(uint32_t* r, uint32_t addr) {
    asm volatile("ldmatrix.sync.aligned.m8n8.x4.shared.b16 {%0,%1,%2,%3}, [%4];"
        : "=r"(r[0]), "=r"(r[1]), "=r"(r[2]), "=r"(r[3]) : "r"(addr));
}
__device__ __forceinline__ void ldsm_x4_t(uint32_t* r, uint32_t addr) {
    asm volatile("ldmatrix.sync.aligned.m8n8.x4.trans.shared.b16 {%0,%1,%2,%3}, [%4];"
        : "=r"(r[0]), "=r"(r[1]), "=r"(r[2]), "=r"(r[3]) : "r"(addr));
}
__device__ __forceinline__ void mma2(float* d, const uint32_t* a, uint32_t b0, uint32_t b1) {
    asm volatile("mma.sync.aligned.m16n8k16.row.col.f32.bf16.bf16.f32 "
        "{%0,%1,%2,%3}, {%4,%5,%6,%7}, {%8,%9}, {%0,%1,%2,%3};"
        : "+f"(d[0]), "+f"(d[1]), "+f"(d[2]), "+f"(d[3])
        : "r"(a[0]), "r"(a[1]), "r"(a[2]), "r"(a[3]), "r"(b0), "r"(b1));
}
__device__ __forceinline__ void cp16(uint32_t s, const void* g) {
    asm volatile("cp.async.cg.shared.global [%0], [%1], 16;" :: "r"(s), "l"(g));
}
#define CP_COMMIT() asm volatile("cp.async.commit_group;" ::: "memory")
#define CP_WAIT(n)  asm volatile("cp.async.wait_group %0;" :: "n"(n) : "memory")

__device__ __forceinline__ void split2(float v, __nv_bfloat16& h, __nv_bfloat16& l) {
    h = __float2bfloat16(v);
    l = __float2bfloat16(v - __bfloat162float(h));
}
__device__ __forceinline__ uint32_t packf2(float lo, float hi) {
    uint32_t r;
    asm("cvt.rn.bf16x2.f32 %0, %1, %2;" : "=r"(r) : "f"(hi), "f"(lo));
    return r;
}

// ---------------- merged weight transpose + split ----------------
__global__ void wconv_all(const float* __restrict__ qkv_w, const float* __restrict__ out_w,
                          const float* __restrict__ fc1_w, const float* __restrict__ fc2_w) {
    __shared__ float t[32][33];
    int bid = blockIdx.x;
    const float* W; __nv_bfloat16 *Th, *Tl; int K, N, tile;
    if (bid < 1728)      { W = qkv_w; Th = g_wqkv_h; Tl = g_wqkv_l; K = DM;  N = NQKV; tile = bid; }
    else if (bid < 2304) { W = out_w; Th = g_wout_h; Tl = g_wout_l; K = DM;  N = DM;   tile = bid - 1728; }
    else if (bid < 4608) { W = fc1_w; Th = g_wfc1_h; Tl = g_wfc1_l; K = DM;  N = DFF;  tile = bid - 2304; }
    else                 { W = fc2_w; Th = g_wfc2_h; Tl = g_wfc2_l; K = DFF; N = DM;   tile = bid - 4608; }
    int ntx = N / 32;
    int n0 = (tile % ntx) * 32, k0 = (tile / ntx) * 32;
    int tx = threadIdx.x & 31, ty = threadIdx.x >> 5;
#pragma unroll
    for (int i = 0; i < 4; i++) {
        int k = ty + i * 8;
        t[k][tx] = W[(size_t)(k0 + k) * N + n0 + tx];
    }
    __syncthreads();
#pragma unroll
    for (int i = 0; i < 4; i++) {
        int nr = ty + i * 8;
        float v = t[tx][nr];
        __nv_bfloat16 h, l;
        split2(v, h, l);
        size_t o = (size_t)(n0 + nr) * K + k0 + tx;
        Th[o] = h; Tl[o] = l;
    }
}

// ---------------- LayerNorm -> bf16 hi/lo planes ----------------
__global__ void ln_kernel(const float* __restrict__ X, const float* __restrict__ g,
                          const float* __restrict__ b,
                          __nv_bfloat16* __restrict__ Yh, __nv_bfloat16* __restrict__ Yl) {
    int row = blockIdx.x;
    const float* xr = X + (size_t)row * DM;
    float v[3];
    float s = 0.f, sq = 0.f;
#pragma unroll
    for (int i = 0; i < 3; i++) {
        v[i] = xr[threadIdx.x + i * 256];
        s += v[i]; sq += v[i] * v[i];
    }
#pragma unroll
    for (int o = 16; o > 0; o >>= 1) {
        s  += __shfl_xor_sync(0xffffffffu, s, o);
        sq += __shfl_xor_sync(0xffffffffu, sq, o);
    }
    __shared__ float red0[8], red1[8];
    int w = threadIdx.x >> 5, lane = threadIdx.x & 31;
    if (lane == 0) { red0[w] = s; red1[w] = sq; }
    __syncthreads();
    s = 0.f; sq = 0.f;
#pragma unroll
    for (int i = 0; i < 8; i++) { s += red0[i]; sq += red1[i]; }
    float mu  = s * (1.f / DM);
    float var = sq * (1.f / DM) - mu * mu;
    float inv = rsqrtf(var + 1e-5f);
#pragma unroll
    for (int i = 0; i < 3; i++) {
        int idx = threadIdx.x + i * 256;
        float y = (v[i] - mu) * inv * g[idx] + b[idx];
        __nv_bfloat16 h, l;
        split2(y, h, l);
        size_t o = (size_t)row * DM + idx;
        Yh[o] = h; Yl[o] = l;
    }
}

// ---------------- HMMA GEMM: BM=128, BN=64, BK=64, 2-stage, 2 CTAs/SM ------
#define A_ST2 144
#define APLANE 18432           // 128*144
#define BPLANE 9216            // 64*144
#define STG (2*APLANE + 2*BPLANE)   // 55296
#define GSM (2 * STG)               // 110592

template <int MODE>
__global__ void __launch_bounds__(256, 2)
gemm_bf(const __nv_bfloat16* __restrict__ Ah, const __nv_bfloat16* __restrict__ Al,
        const __nv_bfloat16* __restrict__ Bh, const __nv_bfloat16* __restrict__ Bl,
        const float* __restrict__ bias, const float* __restrict__ res,
        float* __restrict__ C, __nv_bfloat16* __restrict__ Ch, __nv_bfloat16* __restrict__ Cl,
        int M, int N, int K) {
    extern __shared__ char smem[];
    const uint32_t sb = smem_u32(smem);

    int tid = threadIdx.x, wid = tid >> 5, lane = tid & 31;
    int bn = blockIdx.x, bm = blockIdx.y;
    int wm = wid >> 2, wn = wid & 3;

    uint32_t a_lm = (uint32_t)((wm * 64 + (lane & 15)) * A_ST2 + ((lane >> 4) & 1) * 16);
    uint32_t b_lm = (uint32_t)((wn * 16 + (lane & 15)) * A_ST2 + ((lane >> 4) & 1) * 16);

    float acc[4][2][4];
#pragma unroll
    for (int i = 0; i < 4; i++)
#pragma unroll
        for (int j = 0; j < 2; j++)
#pragma unroll
            for (int q = 0; q < 4; q++) acc[i][j][q] = 0.f;

    const int nkt = K / 64;

    auto load_stage = [&](int kt, int buf) {
        uint32_t st = sb + buf * STG;
        const __nv_bfloat16* a0 = Ah + (size_t)(bm * 128) * K + kt * 64;
        const __nv_bfloat16* a1 = Al + (size_t)(bm * 128) * K + kt * 64;
        const __nv_bfloat16* b0 = Bh + (size_t)(bn * 64) * K + kt * 64;
        const __nv_bfloat16* b1 = Bl + (size_t)(bn * 64) * K + kt * 64;
#pragma unroll
        for (int i = 0; i < 4; i++) {
            int c = tid + i * 256;
            int row = c >> 3, col = c & 7;
            uint32_t so = (uint32_t)(row * A_ST2 + col * 16);
            cp16(st + so, a0 + (size_t)row * K + col * 8);
            cp16(st + APLANE + so, a1 + (size_t)row * K + col * 8);
        }
#pragma unroll
        for (int i = 0; i < 2; i++) {
            int c = tid + i * 256;
            int row = c >> 3, col = c & 7;
            uint32_t so = (uint32_t)(row * A_ST2 + col * 16);
            cp16(st + 2 * APLANE + so, b0 + (size_t)row * K + col * 8);
            cp16(st + 2 * APLANE + BPLANE + so, b1 + (size_t)row * K + col * 8);
        }
    };

    load_stage(0, 0); CP_COMMIT();
    if (nkt > 1) { load_stage(1, 1); CP_COMMIT(); }

    for (int kt = 0; kt < nkt; kt++) {
        if (kt + 1 < nkt) { CP_WAIT(1); } else { CP_WAIT(0); }
        __syncthreads();
        uint32_t st = sb + (kt & 1) * STG;
#pragma unroll
        for (int ks = 0; ks < 4; ks++) {
            uint32_t ah[4][4], al[4][4], th[4], tl[4];
#pragma unroll
            for (int mt = 0; mt < 4; mt++) {
                uint32_t ao = a_lm + (uint32_t)(mt * 16 * A_ST2 + ks * 32);
                ldsm_x4(ah[mt], st + ao);
                ldsm_x4(al[mt], st + APLANE + ao);
            }
            uint32_t bo = b_lm + (uint32_t)(ks * 32);
            ldsm_x4(th, st + 2 * APLANE + bo);
            ldsm_x4(tl, st + 2 * APLANE + BPLANE + bo);
#pragma unroll
            for (int mt = 0; mt < 4; mt++) {
                mma2(acc[mt][0], ah[mt], th[0], th[2]);
                mma2(acc[mt][0], ah[mt], tl[0], tl[2]);
                mma2(acc[mt][0], al[mt], th[0], th[2]);
                mma2(acc[mt][1], ah[mt], th[1], th[3]);
                mma2(acc[mt][1], ah[mt], tl[1], tl[3]);
                mma2(acc[mt][1], al[mt], th[1], th[3]);
            }
        }
        __syncthreads();
        if (kt + 2 < nkt) {
            load_stage(kt + 2, kt & 1);
            CP_COMMIT();
        }
    }

    int r0 = bm * 128 + wm * 64 + (lane >> 2);
    int c0 = bn * 64 + wn * 16 + (lane & 3) * 2;
#pragma unroll
    for (int mt = 0; mt < 4; mt++) {
#pragma unroll
        for (int nt = 0; nt < 2; nt++) {
            int col = c0 + nt * 8;
            float bb0 = bias[col], bb1 = bias[col + 1];
#pragma unroll
            for (int half = 0; half < 2; half++) {
                int row = r0 + mt * 16 + half * 8;
                float v0 = acc[mt][nt][half * 2 + 0] + bb0;
                float v1 = acc[mt][nt][half * 2 + 1] + bb1;
                if (MODE == 1) {
                    v0 = 0.5f * v0 * (1.f + erff(v0 * 0.70710678118654752f));
                    v1 = 0.5f * v1 * (1.f + erff(v1 * 0.70710678118654752f));
                    __nv_bfloat16 h0, l0, h1, l1;
                    split2(v0, h0, l0); split2(v1, h1, l1);
                    size_t o = (size_t)row * N + col;
                    __nv_bfloat162 hp; hp.x = h0; hp.y = h1;
                    __nv_bfloat162 lp; lp.x = l0; lp.y = l1;
                    *(__nv_bfloat162*)(Ch + o) = hp;
                    *(__nv_bfloat162*)(Cl + o) = lp;
                } else if (MODE == 2) {
                    const float* rp = res + (size_t)row * N + col;
                    float2 o; o.x = v0 + rp[0]; o.y = v1 + rp[1];
                    *(float2*)(C + (size_t)row * N + col) = o;
                } else { // MODE 3: scatter into Q/K/V bf16 hi planes only
                    int i3 = col / DM;
                    int rem = col - i3 * DM;
                    int h = rem >> 6, d = rem & 63;
                    int bb = row >> 11, l = row & 2047;
                    size_t idx = (((size_t)bb * NH + h) * LSEQ + l) * HD + d;
                    if (i3 == 0) { v0 *= 0.125f; v1 *= 0.125f; }
                    __nv_bfloat162 hp;
                    hp.x = __float2bfloat16(v0); hp.y = __float2bfloat16(v1);
                    __nv_bfloat16* ph = (i3 == 0) ? g_qh : (i3 == 1) ? g_kh : g_vh;
                    *(__nv_bfloat162*)(ph + idx) = hp;
                }
            }
        }
    }
}

// ---------------- MMA flash attention: pure bf16, Q tile 128, 2 CTAs/SM ----
#define AT_ST 144
#define AT_PLANE (64 * AT_ST)          // 9216  (one 64-row plane)
#define AT_STAGE (2 * AT_PLANE)        // 18432 (K + V)
#define AT_SMEM (2 * AT_STAGE + 512)   // 37376
#define NT_KV (LSEQ / 64)              // 32

__global__ void __launch_bounds__(256, 2)
attn_mma(const int* __restrict__ mask,
         __nv_bfloat16* __restrict__ Oh, __nv_bfloat16* __restrict__ Ol) {
    extern __shared__ char sm[];
    const uint32_t sb = smem_u32(sm);
    float* mb2 = (float*)(sm + 2 * AT_STAGE);

    int tid = threadIdx.x, wid = tid >> 5, lane = tid & 31;
    int qt = blockIdx.x, h = blockIdx.y, b = blockIdx.z;
    size_t bh = ((size_t)b * NH + h) * LSEQ * HD;
    const __nv_bfloat16* Qp = g_qh + bh;
    const __nv_bfloat16* Kp = g_kh + bh;
    const __nv_bfloat16* Vp = g_vh + bh;

    // ---- stage Q tile (128x64 hi) into buf0 region, move to registers
    {
        int qrow0 = qt * 128;
#pragma unroll
        for (int i = 0; i < 4; i++) {
            int c = tid * 4 + i;
            int row = c >> 3, col = c & 7;
            cp16(sb + (uint32_t)(row * AT_ST + col * 16),
                 Qp + (size_t)(qrow0 + row) * HD + col * 8);
        }
    }
    CP_COMMIT();
    CP_WAIT(0);
    __syncthreads();

    uint32_t qf[4][4];
    {
        uint32_t qbase = sb + (uint32_t)((wid * 16 + (lane & 15)) * AT_ST + (lane >> 4) * 16);
#pragma unroll
        for (int ks = 0; ks < 4; ks++)
            ldsm_x4(qf[ks], qbase + ks * 32);
    }
    __syncthreads();

    auto load_kv = [&](int kt, int buf) {
        uint32_t st = sb + buf * AT_STAGE;
        const __nv_bfloat16* k0 = Kp + (size_t)kt * 64 * HD;
        const __nv_bfloat16* v0 = Vp + (size_t)kt * 64 * HD;
#pragma unroll
        for (int i = 0; i < 2; i++) {
            int c = tid * 2 + i;
            int row = c >> 3, col = c & 7;
            uint32_t so = (uint32_t)(row * AT_ST + col * 16);
            cp16(st + so, k0 + (size_t)row * HD + col * 8);
            cp16(st + AT_PLANE + so, v0 + (size_t)row * HD + col * 8);
        }
    };

    if (tid < 64) mb2[tid] = mask[b * LSEQ + tid] ? 0.f : -1e30f;
    load_kv(0, 0);
    CP_COMMIT();

    float m0 = -1e30f, m1 = -1e30f, l0 = 0.f, l1 = 0.f;
    float o[8][4];
#pragma unroll
    for (int nt = 0; nt < 8; nt++)
#pragma unroll
        for (int q = 0; q < 4; q++) o[nt][q] = 0.f;

    for (int kt = 0; kt < NT_KV; kt++) {
        CP_WAIT(0);
        __syncthreads();
        if (kt + 1 < NT_KV) {
            if (tid < 64)
                mb2[((kt + 1) & 1) * 64 + tid] =
                    mask[b * LSEQ + (kt + 1) * 64 + tid] ? 0.f : -1e30f;
            load_kv(kt + 1, (kt + 1) & 1);
            CP_COMMIT();
        }
        uint32_t st = sb + (kt & 1) * AT_STAGE;
        const float* mrow = mb2 + (kt & 1) * 64;

        // ---- S = Q K^T  (bf16 x bf16)
        float s[8][4];
#pragma unroll
        for (int nt = 0; nt < 8; nt++)
#pragma unroll
            for (int q = 0; q < 4; q++) s[nt][q] = 0.f;

#pragma unroll
        for (int ks = 0; ks < 4; ks++) {
#pragma unroll
            for (int g = 0; g < 4; g++) {
                uint32_t addr = st + (uint32_t)((g * 16 + (lane & 15)) * AT_ST
                                                + ks * 32 + (lane >> 4) * 16);
                uint32_t t4[4];
                ldsm_x4(t4, addr);
                mma2(s[g * 2], qf[ks], t4[0], t4[2]);
                mma2(s[g * 2 + 1], qf[ks], t4[1], t4[3]);
            }
        }

        // ---- mask + online softmax
        float rmax0 = -1e30f, rmax1 = -1e30f;
#pragma unroll
        for (int nt = 0; nt < 8; nt++) {
            int k0i = nt * 8 + (lane & 3) * 2;
            float mk0 = mrow[k0i], mk1 = mrow[k0i + 1];
            s[nt][0] += mk0; s[nt][1] += mk1;
            s[nt][2] += mk0; s[nt][3] += mk1;
            rmax0 = fmaxf(rmax0, fmaxf(s[nt][0], s[nt][1]));
            rmax1 = fmaxf(rmax1, fmaxf(s[nt][2], s[nt][3]));
        }
        rmax0 = fmaxf(rmax0, __shfl_xor_sync(0xffffffffu, rmax0, 1));
        rmax0 = fmaxf(rmax0, __shfl_xor_sync(0xffffffffu, rmax0, 2));
        rmax1 = fmaxf(rmax1, __shfl_xor_sync(0xffffffffu, rmax1, 1));
        rmax1 = fmaxf(rmax1, __shfl_xor_sync(0xffffffffu, rmax1, 2));
        float mn0 = fmaxf(m0, rmax0), mn1 = fmaxf(m1, rmax1);
        float al0 = __expf(m0 - mn0), al1 = __expf(m1 - mn1);
        m0 = mn0; m1 = mn1;
        float ps0 = 0.f, ps1 = 0.f;
#pragma unroll
        for (int nt = 0; nt < 8; nt++) {
            s[nt][0] = __expf(s[nt][0] - m0);
            s[nt][1] = __expf(s[nt][1] - m0);
            s[nt][2] = __expf(s[nt][2] - m1);
            s[nt][3] = __expf(s[nt][3] - m1);
            ps0 += s[nt][0] + s[nt][1];
            ps1 += s[nt][2] + s[nt][3];
        }
        ps0 += __shfl_xor_sync(0xffffffffu, ps0, 1);
        ps0 += __shfl_xor_sync(0xffffffffu, ps0, 2);
        ps1 += __shfl_xor_sync(0xffffffffu, ps1, 1);
        ps1 += __shfl_xor_sync(0xffffffffu, ps1, 2);
        l0 = l0 * al0 + ps0;
        l1 = l1 * al1 + ps1;
#pragma unroll
        for (int nt = 0; nt < 8; nt++) {
            o[nt][0] *= al0; o[nt][1] *= al0;
            o[nt][2] *= al1; o[nt][3] *= al1;
        }

        // ---- P -> bf16 A-fragments
        uint32_t pf[4][4];
#pragma unroll
        for (int j = 0; j < 4; j++) {
            pf[j][0] = packf2(s[2 * j][0], s[2 * j][1]);
            pf[j][1] = packf2(s[2 * j][2], s[2 * j][3]);
            pf[j][2] = packf2(s[2 * j + 1][0], s[2 * j + 1][1]);
            pf[j][3] = packf2(s[2 * j + 1][2], s[2 * j + 1][3]);
        }

        // ---- O += P @ V (bf16 V via ldmatrix.trans)
        int g = lane >> 3;
#pragma unroll
        for (int j = 0; j < 4; j++) {
#pragma unroll
            for (int dt = 0; dt < 4; dt++) {
                uint32_t addr = st + (uint32_t)(AT_PLANE
                    + (j * 16 + (g >> 1) * 8 + (lane & 7)) * AT_ST
                    + dt * 32 + (g & 1) * 16);
                uint32_t t4[4];
                ldsm_x4_t(t4, addr);
                mma2(o[dt * 2], pf[j], t4[0], t4[2]);
                mma2(o[dt * 2 + 1], pf[j], t4[1], t4[3]);
            }
        }
    }

    // ---- finalize: O /= l, split hi/lo -> planes [row][DM]
    float i0 = 1.f / l0, i1 = 1.f / l1;
    int rowg = b * LSEQ + qt * 128 + wid * 16 + (lane >> 2);
#pragma unroll
    for (int nt = 0; nt < 8; nt++) {
        int col = h * HD + nt * 8 + (lane & 3) * 2;
        float v0 = o[nt][0] * i0, v1 = o[nt][1] * i0;
        float v2 = o[nt][2] * i1, v3 = o[nt][3] * i1;
        __nv_bfloat16 h0, lo0, h1, lo1, h2, lo2, h3, lo3;
        split2(v0, h0, lo0); split2(v1, h1, lo1);
        split2(v2, h2, lo2); split2(v3, h3, lo3);
        __nv_bfloat162 hp0; hp0.x = h0; hp0.y = h1;
        __nv_bfloat162 lp0; lp0.x = lo0; lp0.y = lo1;
        __nv_bfloat162 hp1; hp1.x = h2; hp1.y = h3;
        __nv_bfloat162 lp1; lp1.x = lo2; lp1.y = lo3;
        *(__nv_bfloat162*)(Oh + (size_t)rowg * DM + col) = hp0;
        *(__nv_bfloat162*)(Ol + (size_t)rowg * DM + col) = lp0;
        *(__nv_bfloat162*)(Oh + (size_t)(rowg + 8) * DM + col) = hp1;
        *(__nv_bfloat162*)(Ol + (size_t)(rowg + 8) * DM + col) = lp1;
    }
}

// ---------------- launch ----------------
template <typename T>
static T* symaddr(const void* sym) {
    void* p = nullptr;
    cudaGetSymbolAddress(&p, sym);
    return (T*)p;
}

extern "C" void kernel_launch(void* const* d_in, const int* in_sizes, int n_in,
                              void* d_out, int out_size) {
    (void)in_sizes; (void)n_in; (void)out_size;
    const float* x      = (const float*)d_in[0];
    const int*   mask   = (const int*)  d_in[1];
    const float* ln1_g  = (const float*)d_in[2];
    const float* ln1_b  = (const float*)d_in[3];
    const float* qkv_w  = (const float*)d_in[4];
    const float* qkv_b  = (const float*)d_in[5];
    const float* out_w  = (const float*)d_in[6];
    const float* out_b  = (const float*)d_in[7];
    const float* ln2_g  = (const float*)d_in[8];
    const float* ln2_b  = (const float*)d_in[9];
    const float* fc1_w  = (const float*)d_in[10];
    const float* fc1_b  = (const float*)d_in[11];
    const float* fc2_w  = (const float*)d_in[12];
    const float* fc2_b  = (const float*)d_in[13];
    float* out = (float*)d_out;

    float* p_x1  = symaddr<float>(g_x1);
    __nv_bfloat16* p_hh  = symaddr<__nv_bfloat16>(g_h_h);
    __nv_bfloat16* p_hl  = symaddr<__nv_bfloat16>(g_h_l);
    __nv_bfloat16* p_ath = symaddr<__nv_bfloat16>(g_at_h);
    __nv_bfloat16* p_atl = symaddr<__nv_bfloat16>(g_at_l);
    __nv_bfloat16* p_ffh = symaddr<__nv_bfloat16>(g_ff_h);
    __nv_bfloat16* p_ffl = symaddr<__nv_bfloat16>(g_ff_l);
    __nv_bfloat16* wq_h = symaddr<__nv_bfloat16>(g_wqkv_h), *wq_l = symaddr<__nv_bfloat16>(g_wqkv_l);
    __nv_bfloat16* wo_h = symaddr<__nv_bfloat16>(g_wout_h), *wo_l = symaddr<__nv_bfloat16>(g_wout_l);
    __nv_bfloat16* w1_h = symaddr<__nv_bfloat16>(g_wfc1_h), *w1_l = symaddr<__nv_bfloat16>(g_wfc1_l);
    __nv_bfloat16* w2_h = symaddr<__nv_bfloat16>(g_wfc2_h), *w2_l = symaddr<__nv_bfloat16>(g_wfc2_l);

    cudaFuncSetAttribute(gemm_bf<1>, cudaFuncAttributeMaxDynamicSharedMemorySize, GSM);
    cudaFuncSetAttribute(gemm_bf<2>, cudaFuncAttributeMaxDynamicSharedMemorySize, GSM);
    cudaFuncSetAttribute(gemm_bf<3>, cudaFuncAttributeMaxDynamicSharedMemorySize, GSM);
    cudaFuncSetAttribute(attn_mma, cudaFuncAttributeMaxDynamicSharedMemorySize, AT_SMEM);

    // 1. LN1
    ln_kernel<<<MROWS, 256>>>(x, ln1_g, ln1_b, p_hh, p_hl);
    // 2. merged weight conversions
    wconv_all<<<6912, 256>>>(qkv_w, out_w, fc1_w, fc2_w);
    // 3. QKV projection -> Q/K/V bf16 planes (Q pre-scaled)
    gemm_bf<3><<<dim3(NQKV / 64, MROWS / 128), 256, GSM>>>(
        p_hh, p_hl, wq_h, wq_l, qkv_b, nullptr, nullptr, nullptr, nullptr, MROWS, NQKV, DM);
    // 4. MMA flash attention -> bf16 hi/lo planes
    attn_mma<<<dim3(LSEQ / 128, NH, BB), 256, AT_SMEM>>>(mask, p_ath, p_atl);
    // 5. output projection + residual
    gemm_bf<2><<<dim3(DM / 64, MROWS / 128), 256, GSM>>>(
        p_ath, p_atl, wo_h, wo_l, out_b, x, p_x1, nullptr, nullptr, MROWS, DM, DM);
    // 6. LN2
    ln_kernel<<<MROWS, 256>>>(p_x1, ln2_g, ln2_b, p_hh, p_hl);
    // 7. fc1 + GELU -> bf16 planes
    gemm_bf<1><<<dim3(DFF / 64, MROWS / 128), 256, GSM>>>(
        p_hh, p_hl, w1_h, w1_l, fc1_b, nullptr, nullptr, p_ffh, p_ffl, MROWS, DFF, DM);
    // 8. fc2 + residual -> output
    gemm_bf<2><<<dim3(DM / 64, MROWS / 128), 256, GSM>>>(
        p_ffh, p_ffl, w2_h, w2_l, fc2_b, p_x1, out, nullptr, nullptr, MROWS, DM, DFF);
}